// round 10
// baseline (speedup 1.0000x reference)
#include <cuda_runtime.h>
#include <cuda_fp16.h>
#include <math.h>
#include <stdint.h>

// Problem dims (fixed)
#define BB 16
#define NSEQ 2048
#define MM 512
#define HH 512
#define BN_ROWS (BB * NSEQ)   // 32768
#define GRP 4                 // batches per attention group (att fits L2)

// ---------------------------------------------------------------------------
// Split layout (fp16): for a logical [R x K] matrix, 4 bytes/elem as groups of
// 32 columns: each 128B group = 32 fp16 "hi" then 32 fp16 "lo".
// byte(r, c) = r*rowBytes + (c>>5)*128 + (c&31)*2   (hi; lo at +64)
// Plain fp16 layout: byte(r, c) = r*rowBytes + c*2.
// ---------------------------------------------------------------------------
__device__ __align__(128) uint8_t g_h_s  [(long long)BN_ROWS * HH * 4];     // h split
__device__ __align__(128) uint8_t g_qk_s [(long long)BN_ROWS * 1024 * 4];   // q|k split
__device__ __align__(128) uint8_t g_v16  [(long long)BN_ROWS * HH * 2];     // v plain
__device__ __align__(128) uint8_t g_vt16 [(long long)BN_ROWS * HH * 2];     // v^T plain
__device__ __align__(128) uint8_t g_o_s  [(long long)BN_ROWS * HH * 4];     // o split
__device__ __align__(128) uint8_t g_hid_s[(long long)BN_ROWS * HH * 4];     // hid split
__device__ __align__(128) uint8_t g_wqk_s[1024LL * 512 * 4];                // Wq^T|Wk^T split
__device__ __align__(128) uint8_t g_wv16 [512LL * 512 * 2];                 // Wv^T plain
__device__ __align__(128) uint8_t g_w116 [512LL * 512 * 2];                 // W1^T plain
__device__ __align__(128) uint8_t g_w216 [512LL * 512 * 2];                 // W2^T plain
__device__ float g_att[(long long)BB * NSEQ * NSEQ];
__device__ __align__(128) __half g_atth[(long long)BB * NSEQ * NSEQ];
__device__ float g_bqk[1024];

// ---------------------------------------------------------------------------
// Helpers
// ---------------------------------------------------------------------------
__device__ __forceinline__ uint32_t smem_u32(const void* p) {
    uint32_t a;
    asm("{ .reg .u64 t; cvta.to.shared.u64 t, %1; cvt.u32.u64 %0, t; }" : "=r"(a) : "l"(p));
    return a;
}
__device__ __forceinline__ void ldsm4(uint32_t* r, uint32_t addr) {
    asm volatile("ldmatrix.sync.aligned.m8n8.x4.shared.b16 {%0,%1,%2,%3}, [%4];"
                 : "=r"(r[0]), "=r"(r[1]), "=r"(r[2]), "=r"(r[3]) : "r"(addr));
}
__device__ __forceinline__ void mma_f16(float* c, const uint32_t* a,
                                        uint32_t b0, uint32_t b1) {
    asm volatile(
        "mma.sync.aligned.m16n8k16.row.col.f32.f16.f16.f32 "
        "{%0,%1,%2,%3}, {%4,%5,%6,%7}, {%8,%9}, {%0,%1,%2,%3};"
        : "+f"(c[0]), "+f"(c[1]), "+f"(c[2]), "+f"(c[3])
        : "r"(a[0]), "r"(a[1]), "r"(a[2]), "r"(a[3]), "r"(b0), "r"(b1));
}
__device__ __forceinline__ void cp16(uint32_t dst, const void* src) {
    asm volatile("cp.async.cg.shared.global [%0], [%1], 16;" :: "r"(dst), "l"(src));
}
__device__ __forceinline__ void cp_commit() {
    asm volatile("cp.async.commit_group;");
}
template <int N> __device__ __forceinline__ void cp_wait() {
    asm volatile("cp.async.wait_group %0;" :: "n"(N));
}
__device__ __forceinline__ void split2h(float x, float y, uint32_t& hi, uint32_t& lo) {
    __half2 h = __floats2half2_rn(x, y);
    __half2 l = __floats2half2_rn(x - __half2float(h.x), y - __half2float(h.y));
    hi = *(uint32_t*)&h;
    lo = *(uint32_t*)&l;
}

// Plain-fp16 smem tile addressing (64B of data per row, 2 rows packed per 128B
// line, 8-chunk XOR swizzle): conflict-free for ldmatrix and cp.async.
__device__ __forceinline__ uint32_t plainb_addr(uint32_t base, int r, int c) {
    return base + ((r >> 1) << 7) + (((((r & 1) << 2) + c) ^ ((r >> 1) & 7)) << 4);
}

// OUTMODE: 0 = fp32, 1 = split fp16, 2 = plain fp16

// ---------------------------------------------------------------------------
// gemm3: A split fp16, B split fp16, 3 MMAs (HH, HL, LH), chain-batched.
// C[M,N] = A[M,K] @ B[N,K]^T (+bias). CTA 128x128, warp 32x64, K staged 32,
// 3-deep cp.async, 256 threads, 2 CTAs/SM.
// ---------------------------------------------------------------------------
#define G3_STAGES 3
#define G3_STAGE 32768
#define G3_SMEM (G3_STAGES * G3_STAGE)

template <bool HAS_BIAS, int OUTMODE>
__global__ __launch_bounds__(256, 2)
void hmma_gemm3(const uint8_t* __restrict__ A, const uint8_t* __restrict__ B,
                const float* __restrict__ bias, float* __restrict__ Cf,
                uint8_t* __restrict__ Cs,
                int K, long long ldaB, long long ldbB, long long ldcB,
                long long sA, long long sB, long long sC)
{
    extern __shared__ uint8_t sm[];
    const long long bz = blockIdx.z;
    A += bz * sA;
    B += bz * sB;

    const int tid = threadIdx.x;
    const int wid = tid >> 5, lane = tid & 31;
    const int wm = wid & 3, wn = wid >> 2;
    const int lr = lane & 15, lc = lane >> 4;
    const int m0 = blockIdx.y * 128, n0 = blockIdx.x * 128;

    const int lrow = tid >> 1;
    const int cb = (tid & 1) * 4;
    const int rsw = lrow & 7;

    const uint32_t smb = smem_u32(sm);
    const uint8_t* srcA0 = A + (long long)(m0 + lrow) * ldaB + cb * 16;
    const uint8_t* srcB0 = B + (long long)(n0 + lrow) * ldbB + cb * 16;

    float acc[2][8][4];
#pragma unroll
    for (int i = 0; i < 2; ++i)
#pragma unroll
        for (int j = 0; j < 8; ++j)
#pragma unroll
            for (int t = 0; t < 4; ++t) acc[i][j][t] = 0.0f;

    const int S = K / 32;

#define G3_ISSUE(s)                                                           \
    do {                                                                      \
        const uint32_t dra = smb + ((s) % G3_STAGES) * G3_STAGE + lrow * 128; \
        const uint8_t* pa = srcA0 + (s) * 128;                                \
        const uint8_t* pb = srcB0 + (s) * 128;                                \
        _Pragma("unroll")                                                     \
        for (int c = 0; c < 4; ++c)                                           \
            cp16(dra + (((cb + c) ^ rsw) << 4), pa + c * 16);                 \
        _Pragma("unroll")                                                     \
        for (int c = 0; c < 4; ++c)                                           \
            cp16(dra + 16384 + (((cb + c) ^ rsw) << 4), pb + c * 16);         \
        cp_commit();                                                          \
    } while (0)

    G3_ISSUE(0);
    G3_ISSUE(1);

    for (int s = 0; s < S; ++s) {
        if (s + 1 < S) cp_wait<1>(); else cp_wait<0>();
        __syncthreads();
        if (s + 2 < S) G3_ISSUE(s + 2);

        const uint32_t bufA = smb + (s % G3_STAGES) * G3_STAGE;
        const uint32_t bufB = bufA + 16384;

#pragma unroll
        for (int kk = 0; kk < 2; ++kk) {
            uint32_t aH[2][4], aL[2][4];
            const int byteh = kk * 32 + lc * 16;
#pragma unroll
            for (int mi = 0; mi < 2; ++mi) {
                const int r = wm * 32 + mi * 16 + lr;
                const uint32_t rb = bufA + r * 128;
                const int rs = r & 7;
                ldsm4(aH[mi], rb + ((((byteh) >> 4) ^ rs) << 4));
                ldsm4(aL[mi], rb + ((((byteh + 64) >> 4) ^ rs) << 4));
            }
#pragma unroll
            for (int g = 0; g < 4; ++g) {
                const int r = wn * 64 + g * 16 + lr;
                const uint32_t rb = bufB + r * 128;
                const int rs = r & 7;
                uint32_t bh[4], bl[4];
                ldsm4(bh, rb + ((((byteh) >> 4) ^ rs) << 4));
                ldsm4(bl, rb + ((((byteh + 64) >> 4) ^ rs) << 4));
#pragma unroll
                for (int mi = 0; mi < 2; ++mi) {          // HH
                    mma_f16(acc[mi][2 * g],     aH[mi], bh[0], bh[2]);
                    mma_f16(acc[mi][2 * g + 1], aH[mi], bh[1], bh[3]);
                }
#pragma unroll
                for (int mi = 0; mi < 2; ++mi) {          // HL
                    mma_f16(acc[mi][2 * g],     aH[mi], bl[0], bl[2]);
                    mma_f16(acc[mi][2 * g + 1], aH[mi], bl[1], bl[3]);
                }
#pragma unroll
                for (int mi = 0; mi < 2; ++mi) {          // LH
                    mma_f16(acc[mi][2 * g],     aL[mi], bh[0], bh[2]);
                    mma_f16(acc[mi][2 * g + 1], aL[mi], bh[1], bh[3]);
                }
            }
        }
    }
#undef G3_ISSUE

#pragma unroll
    for (int mi = 0; mi < 2; ++mi) {
        const long long r0 = m0 + wm * 32 + mi * 16 + (lane >> 2);
#pragma unroll
        for (int nj = 0; nj < 8; ++nj) {
            const int col = n0 + wn * 64 + nj * 8 + 2 * (lane & 3);
            float bx = 0.0f, by = 0.0f;
            if (HAS_BIAS) {
                const float2 bvv = *(const float2*)(bias + col);
                bx = bvv.x; by = bvv.y;
            }
            const float x0 = acc[mi][nj][0] + bx;
            const float x1 = acc[mi][nj][1] + by;
            const float x2 = acc[mi][nj][2] + bx;
            const float x3 = acc[mi][nj][3] + by;
            if (OUTMODE == 0) {
                uint8_t* base = (uint8_t*)Cf + bz * sC;
                *(float2*)(base + r0 * ldcB + col * 4)       = make_float2(x0, x1);
                *(float2*)(base + (r0 + 8) * ldcB + col * 4) = make_float2(x2, x3);
            } else {
                uint8_t* base = Cs + bz * sC;
                const long long cb0 = (long long)(col >> 5) * 128 + (col & 31) * 2;
                uint32_t hi, lo;
                split2h(x0, x1, hi, lo);
                uint8_t* p = base + r0 * ldcB + cb0;
                *(uint32_t*)p = hi;
                *(uint32_t*)(p + 64) = lo;
                split2h(x2, x3, hi, lo);
                p = base + (r0 + 8) * ldcB + cb0;
                *(uint32_t*)p = hi;
                *(uint32_t*)(p + 64) = lo;
            }
        }
    }
}

// ---------------------------------------------------------------------------
// gemm2: A split fp16, B plain fp16 (single), 2 MMAs, chain-batched.
// 4-deep cp.async (96KB smem, 2 CTAs/SM).
// ---------------------------------------------------------------------------
#define G2_STAGES 4
#define G2_STAGE 24576
#define G2_SMEM (G2_STAGES * G2_STAGE)

template <bool HAS_BIAS, bool RELU, int OUTMODE>
__global__ __launch_bounds__(256, 2)
void hmma_gemm2(const uint8_t* __restrict__ A, const uint8_t* __restrict__ B,
                const float* __restrict__ bias, float* __restrict__ Cf,
                uint8_t* __restrict__ Cs,
                int K, long long ldaB, long long ldbB, long long ldcB)
{
    extern __shared__ uint8_t sm[];
    const int tid = threadIdx.x;
    const int wid = tid >> 5, lane = tid & 31;
    const int wm = wid & 3, wn = wid >> 2;
    const int lr = lane & 15, lc = lane >> 4;
    const int m0 = blockIdx.y * 128, n0 = blockIdx.x * 128;

    const int lrow = tid >> 1;
    const int cbA = (tid & 1) * 4;
    const int cbB = (tid & 1) * 2;
    const int rsw = lrow & 7;

    const uint32_t smb = smem_u32(sm);
    const uint8_t* srcA0 = A + (long long)(m0 + lrow) * ldaB + cbA * 16;
    const uint8_t* srcB0 = B + (long long)(n0 + lrow) * ldbB + cbB * 16;

    float acc[2][8][4];
#pragma unroll
    for (int i = 0; i < 2; ++i)
#pragma unroll
        for (int j = 0; j < 8; ++j)
#pragma unroll
            for (int t = 0; t < 4; ++t) acc[i][j][t] = 0.0f;

    const int S = K / 32;

#define G2_ISSUE(s)                                                           \
    do {                                                                      \
        const uint32_t stb = smb + ((s) % G2_STAGES) * G2_STAGE;              \
        const uint8_t* pa = srcA0 + (s) * 128;                                \
        const uint8_t* pb = srcB0 + (s) * 64;                                 \
        const uint32_t dra = stb + lrow * 128;                                \
        _Pragma("unroll")                                                     \
        for (int c = 0; c < 4; ++c)                                           \
            cp16(dra + (((cbA + c) ^ rsw) << 4), pa + c * 16);                \
        _Pragma("unroll")                                                     \
        for (int c = 0; c < 2; ++c)                                           \
            cp16(plainb_addr(stb + 16384, lrow, cbB + c), pb + c * 16);       \
        cp_commit();                                                          \
    } while (0)

    G2_ISSUE(0);
    G2_ISSUE(1);
    G2_ISSUE(2);

    for (int s = 0; s < S; ++s) {
        if (s + 1 < S) cp_wait<2>(); else cp_wait<0>();
        __syncthreads();
        if (s + 3 < S) G2_ISSUE(s + 3);

        const uint32_t bufA = smb + (s % G2_STAGES) * G2_STAGE;
        const uint32_t bufB = bufA + 16384;

#pragma unroll
        for (int kk = 0; kk < 2; ++kk) {
            uint32_t aH[2][4], aL[2][4];
            const int byteh = kk * 32 + lc * 16;
#pragma unroll
            for (int mi = 0; mi < 2; ++mi) {
                const int r = wm * 32 + mi * 16 + lr;
                const uint32_t rb = bufA + r * 128;
                const int rs = r & 7;
                ldsm4(aH[mi], rb + ((((byteh) >> 4) ^ rs) << 4));
                ldsm4(aL[mi], rb + ((((byteh + 64) >> 4) ^ rs) << 4));
            }
#pragma unroll
            for (int g = 0; g < 4; ++g) {
                const int r = wn * 64 + g * 16 + lr;
                const int c = kk * 2 + lc;
                uint32_t b[4];
                ldsm4(b, plainb_addr(bufB, r, c));
#pragma unroll
                for (int mi = 0; mi < 2; ++mi) {          // H*b
                    mma_f16(acc[mi][2 * g],     aH[mi], b[0], b[2]);
                    mma_f16(acc[mi][2 * g + 1], aH[mi], b[1], b[3]);
                }
#pragma unroll
                for (int mi = 0; mi < 2; ++mi) {          // L*b
                    mma_f16(acc[mi][2 * g],     aL[mi], b[0], b[2]);
                    mma_f16(acc[mi][2 * g + 1], aL[mi], b[1], b[3]);
                }
            }
        }
    }
#undef G2_ISSUE

#pragma unroll
    for (int mi = 0; mi < 2; ++mi) {
        const long long r0 = m0 + wm * 32 + mi * 16 + (lane >> 2);
#pragma unroll
        for (int nj = 0; nj < 8; ++nj) {
            const int col = n0 + wn * 64 + nj * 8 + 2 * (lane & 3);
            float bx = 0.0f, by = 0.0f;
            if (HAS_BIAS) {
                const float2 bvv = *(const float2*)(bias + col);
                bx = bvv.x; by = bvv.y;
            }
            float x0 = acc[mi][nj][0] + bx;
            float x1 = acc[mi][nj][1] + by;
            float x2 = acc[mi][nj][2] + bx;
            float x3 = acc[mi][nj][3] + by;
            if (RELU) {
                x0 = fmaxf(x0, 0.0f); x1 = fmaxf(x1, 0.0f);
                x2 = fmaxf(x2, 0.0f); x3 = fmaxf(x3, 0.0f);
            }
            if (OUTMODE == 0) {
                *(float2*)((uint8_t*)Cf + r0 * ldcB + col * 4)       = make_float2(x0, x1);
                *(float2*)((uint8_t*)Cf + (r0 + 8) * ldcB + col * 4) = make_float2(x2, x3);
            } else if (OUTMODE == 1) {
                const long long cb0 = (long long)(col >> 5) * 128 + (col & 31) * 2;
                uint32_t hi, lo;
                split2h(x0, x1, hi, lo);
                uint8_t* p = Cs + r0 * ldcB + cb0;
                *(uint32_t*)p = hi;
                *(uint32_t*)(p + 64) = lo;
                split2h(x2, x3, hi, lo);
                p = Cs + (r0 + 8) * ldcB + cb0;
                *(uint32_t*)p = hi;
                *(uint32_t*)(p + 64) = lo;
            } else {
                __half2 v01 = __floats2half2_rn(x0, x1);
                __half2 v23 = __floats2half2_rn(x2, x3);
                *(uint32_t*)(Cs + r0 * ldcB + col * 2)       = *(uint32_t*)&v01;
                *(uint32_t*)(Cs + (r0 + 8) * ldcB + col * 2) = *(uint32_t*)&v23;
            }
        }
    }
}

// ---------------------------------------------------------------------------
// av1: o[b] = att[b] @ vt[b]^T; both plain fp16, 1 MMA. 4-deep cp.async.
// ---------------------------------------------------------------------------
#define AV_STAGES 4
#define AV_STAGE 16384
#define AV_SMEM (AV_STAGES * AV_STAGE)

__global__ __launch_bounds__(256, 2)
void hmma_av1(const uint8_t* __restrict__ A, const uint8_t* __restrict__ B,
              uint8_t* __restrict__ Cs)
{
    extern __shared__ uint8_t sm[];
    const long long bz = blockIdx.z;
    A += bz * (long long)NSEQ * 4096;       // att rows, 2048 fp16
    B += bz * 512LL * 4096;                 // vt rows, 2048 fp16

    const int tid = threadIdx.x;
    const int wid = tid >> 5, lane = tid & 31;
    const int wm = wid & 3, wn = wid >> 2;
    const int lr = lane & 15, lc = lane >> 4;
    const int m0 = blockIdx.y * 128, n0 = blockIdx.x * 128;

    const int lrow = tid >> 1;
    const int cb2 = (tid & 1) * 2;

    const uint32_t smb = smem_u32(sm);
    const uint8_t* srcA0 = A + (long long)(m0 + lrow) * 4096 + cb2 * 16;
    const uint8_t* srcB0 = B + (long long)(n0 + lrow) * 4096 + cb2 * 16;

    float acc[2][8][4];
#pragma unroll
    for (int i = 0; i < 2; ++i)
#pragma unroll
        for (int j = 0; j < 8; ++j)
#pragma unroll
            for (int t = 0; t < 4; ++t) acc[i][j][t] = 0.0f;

    const int S = NSEQ / 32;  // 64

#define AV_ISSUE(s)                                                           \
    do {                                                                      \
        const uint32_t stb = smb + ((s) % AV_STAGES) * AV_STAGE;              \
        const uint8_t* pa = srcA0 + (s) * 64;                                 \
        const uint8_t* pb = srcB0 + (s) * 64;                                 \
        _Pragma("unroll")                                                     \
        for (int c = 0; c < 2; ++c)                                           \
            cp16(plainb_addr(stb, lrow, cb2 + c), pa + c * 16);               \
        _Pragma("unroll")                                                     \
        for (int c = 0; c < 2; ++c)                                           \
            cp16(plainb_addr(stb + 8192, lrow, cb2 + c), pb + c * 16);        \
        cp_commit();                                                          \
    } while (0)

    AV_ISSUE(0);
    AV_ISSUE(1);
    AV_ISSUE(2);

    for (int s = 0; s < S; ++s) {
        if (s + 1 < S) cp_wait<2>(); else cp_wait<0>();
        __syncthreads();
        if (s + 3 < S) AV_ISSUE(s + 3);

        const uint32_t bufA = smb + (s % AV_STAGES) * AV_STAGE;
        const uint32_t bufB = bufA + 8192;

#pragma unroll
        for (int kk = 0; kk < 2; ++kk) {
            const int c = kk * 2 + lc;
            uint32_t aF[2][4];
#pragma unroll
            for (int mi = 0; mi < 2; ++mi) {
                const int r = wm * 32 + mi * 16 + lr;
                ldsm4(aF[mi], plainb_addr(bufA, r, c));
            }
#pragma unroll
            for (int g = 0; g < 4; ++g) {
                const int r = wn * 64 + g * 16 + lr;
                uint32_t b[4];
                ldsm4(b, plainb_addr(bufB, r, c));
#pragma unroll
                for (int mi = 0; mi < 2; ++mi) {
                    mma_f16(acc[mi][2 * g],     aF[mi], b[0], b[2]);
                    mma_f16(acc[mi][2 * g + 1], aF[mi], b[1], b[3]);
                }
            }
        }
    }
#undef AV_ISSUE

    // epilogue: o split fp16, rows local to this kernel's pointer base
#pragma unroll
    for (int mi = 0; mi < 2; ++mi) {
        const long long r0 = bz * NSEQ + m0 + wm * 32 + mi * 16 + (lane >> 2);
#pragma unroll
        for (int nj = 0; nj < 8; ++nj) {
            const int col = n0 + wn * 64 + nj * 8 + 2 * (lane & 3);
            const long long cb0 = (long long)(col >> 5) * 128 + (col & 31) * 2;
            uint32_t hi, lo;
            split2h(acc[mi][nj][0], acc[mi][nj][1], hi, lo);
            uint8_t* p = Cs + r0 * 2048 + cb0;
            *(uint32_t*)p = hi;
            *(uint32_t*)(p + 64) = lo;
            split2h(acc[mi][nj][2], acc[mi][nj][3], hi, lo);
            p = Cs + (r0 + 8) * 2048 + cb0;
            *(uint32_t*)p = hi;
            *(uint32_t*)(p + 64) = lo;
        }
    }
}

// ---------------------------------------------------------------------------
// Prep kernels
// ---------------------------------------------------------------------------
__global__ __launch_bounds__(256)
void split16_rows512(const float* __restrict__ in, uint8_t* __restrict__ out)
{
    const long long i8 = ((long long)blockIdx.x * 256 + threadIdx.x) * 8;
    const long long row = i8 >> 9;
    const int col = (int)(i8 & 511);
    const float4 a = *(const float4*)(in + i8);
    const float4 b = *(const float4*)(in + i8 + 4);
    uint4 hi, lo;
    split2h(a.x, a.y, hi.x, lo.x);
    split2h(a.z, a.w, hi.y, lo.y);
    split2h(b.x, b.y, hi.z, lo.z);
    split2h(b.z, b.w, hi.w, lo.w);
    uint8_t* p = out + row * 2048 + (col >> 5) * 128 + (col & 31) * 2;
    *(uint4*)p = hi;
    *(uint4*)(p + 64) = lo;
}

__global__ __launch_bounds__(256)
void transpose_split_w16(const float* __restrict__ in, uint8_t* __restrict__ out,
                         long long rowOff)
{
    __shared__ float t[32][33];
    const int c0 = blockIdx.x * 32;
    const int r0 = blockIdx.y * 32;
    const int x = threadIdx.x;
    const int y = threadIdx.y;
#pragma unroll
    for (int j = 0; j < 32; j += 8)
        t[y + j][x] = in[(long long)(r0 + y + j) * 512 + c0 + x];
    __syncthreads();
#pragma unroll
    for (int j = 0; j < 32; j += 8) {
        const float val = t[x][y + j];
        const long long row = rowOff + c0 + y + j;
        const int col = r0 + x;
        __half hi = __float2half_rn(val);
        __half lo = __float2half_rn(val - __half2float(hi));
        uint8_t* p = out + row * 2048 + (col >> 5) * 128 + (col & 31) * 2;
        *(__half*)p = hi;
        *(__half*)(p + 64) = lo;
    }
}

__global__ __launch_bounds__(256)
void transpose_plain_w16(const float* __restrict__ in, __half* __restrict__ out)
{
    __shared__ float t[32][33];
    const int c0 = blockIdx.x * 32;
    const int r0 = blockIdx.y * 32;
    const int x = threadIdx.x;
    const int y = threadIdx.y;
#pragma unroll
    for (int j = 0; j < 32; j += 8)
        t[y + j][x] = in[(long long)(r0 + y + j) * 512 + c0 + x];
    __syncthreads();
#pragma unroll
    for (int j = 0; j < 32; j += 8)
        out[(long long)(c0 + y + j) * 512 + r0 + x] = __float2half_rn(t[x][y + j]);
}

__global__ __launch_bounds__(256)
void vt_transpose16(const __half* __restrict__ v, __half* __restrict__ vt)
{
    __shared__ __half t[32][33];
    const long long b = blockIdx.z;
    const int h0 = blockIdx.x * 32;
    const int n0 = blockIdx.y * 32;
    const int x = threadIdx.x;
    const int y = threadIdx.y;
#pragma unroll
    for (int j = 0; j < 32; j += 8)
        t[y + j][x] = v[(b * 2048 + n0 + y + j) * 512 + h0 + x];
    __syncthreads();
#pragma unroll
    for (int j = 0; j < 32; j += 8)
        vt[b * 512 * 2048 + (long long)(h0 + y + j) * 2048 + n0 + x] = t[x][y + j];
}

// ---------------------------------------------------------------------------
// Row softmax (2048) fp32 -> fp16, threshold-gated exp (bit-equivalent output).
// ---------------------------------------------------------------------------
__global__ __launch_bounds__(256)
void softmax_f16_kernel(const float* __restrict__ att, __half* __restrict__ outh)
{
    const float* row = att + (long long)blockIdx.x * NSEQ;
    __half* orow = outh + (long long)blockIdx.x * NSEQ;
    __shared__ float sred[8];
    const int tid = threadIdx.x;
    const int wid = tid >> 5;
    const int lane = tid & 31;
    const int c0 = tid * 8;

    float r[8];
    *(float4*)&r[0] = *(const float4*)(row + c0);
    *(float4*)&r[4] = *(const float4*)(row + c0 + 4);

    float lmax = r[0];
#pragma unroll
    for (int p = 1; p < 8; ++p) lmax = fmaxf(lmax, r[p]);
    float m = lmax;
#pragma unroll
    for (int off = 16; off > 0; off >>= 1)
        m = fmaxf(m, __shfl_xor_sync(0xFFFFFFFFu, m, off));
    if (lane == 0) sred[wid] = m;
    __syncthreads();
    float M = sred[0];
#pragma unroll
    for (int w = 1; w < 8; ++w) M = fmaxf(M, sred[w]);

    float sum = 0.0f;
    if (lmax - M > -25.0f) {
#pragma unroll
        for (int p = 0; p < 8; ++p) {
            r[p] = __expf(r[p] - M);
            sum += r[p];
        }
    } else {
#pragma unroll
        for (int p = 0; p < 8; ++p) r[p] = 0.0f;
    }

#pragma unroll
    for (int off = 16; off > 0; off >>= 1)
        sum += __shfl_xor_sync(0xFFFFFFFFu, sum, off);
    __syncthreads();
    if (lane == 0) sred[wid] = sum;
    __syncthreads();
    float S = sred[0];
#pragma unroll
    for (int w = 1; w < 8; ++w) S += sred[w];
    const float inv = 1.0f / S;

    __half2 hh[4];
#pragma unroll
    for (int p = 0; p < 4; ++p)
        hh[p] = __floats2half2_rn(r[2 * p] * inv, r[2 * p + 1] * inv);
    *(uint4*)(orow + c0) = *(uint4*)hh;
}

__global__ void concat_bias_qk(const float* bq, const float* bk, float* dst)
{
    const int t = blockIdx.x * 256 + threadIdx.x;
    if (t < 512) {
        dst[t] = bq[t];
        dst[512 + t] = bk[t];
    }
}

// ---------------------------------------------------------------------------
// Launch.  Attention middle is group-chained (GRP batches per stage) so the
// per-group att working set (67MB fp32 + 34MB fp16) stays L2-resident across
// logits -> softmax -> AV.  Launch order puts qk-proj at slot 6 for ncu.
// ---------------------------------------------------------------------------
extern "C" void kernel_launch(void* const* d_in, const int* in_sizes, int n_in,
                              void* d_out, int out_size)
{
    (void)in_sizes; (void)n_in; (void)out_size;
    const float* h  = (const float*)d_in[1];
    const float* Wv = (const float*)d_in[2];
    const float* bv = (const float*)d_in[3];
    const float* Wk = (const float*)d_in[4];
    const float* bk = (const float*)d_in[5];
    const float* Wq = (const float*)d_in[6];
    const float* bq = (const float*)d_in[7];
    const float* W1 = (const float*)d_in[8];
    const float* b1 = (const float*)d_in[9];
    const float* W2 = (const float*)d_in[10];
    const float* b2 = (const float*)d_in[11];
    float* out = (float*)d_out;

    uint8_t *hs, *qks, *v16, *vt16, *os, *hids, *wqks, *wv16, *w116, *w216;
    float *att, *bqk;
    __half* atth;
    cudaGetSymbolAddress((void**)&hs,   g_h_s);
    cudaGetSymbolAddress((void**)&qks,  g_qk_s);
    cudaGetSymbolAddress((void**)&v16,  g_v16);
    cudaGetSymbolAddress((void**)&vt16, g_vt16);
    cudaGetSymbolAddress((void**)&os,   g_o_s);
    cudaGetSymbolAddress((void**)&hids, g_hid_s);
    cudaGetSymbolAddress((void**)&wqks, g_wqk_s);
    cudaGetSymbolAddress((void**)&wv16, g_wv16);
    cudaGetSymbolAddress((void**)&w116, g_w116);
    cudaGetSymbolAddress((void**)&w216, g_w216);
    cudaGetSymbolAddress((void**)&att,  g_att);
    cudaGetSymbolAddress((void**)&atth, g_atth);
    cudaGetSymbolAddress((void**)&bqk,  g_bqk);

    cudaFuncSetAttribute(hmma_gemm3<true,  1>, cudaFuncAttributeMaxDynamicSharedMemorySize, G3_SMEM);
    cudaFuncSetAttribute(hmma_gemm3<false, 0>, cudaFuncAttributeMaxDynamicSharedMemorySize, G3_SMEM);
    cudaFuncSetAttribute(hmma_gemm2<true, false, 2>, cudaFuncAttributeMaxDynamicSharedMemorySize, G2_SMEM);
    cudaFuncSetAttribute(hmma_gemm2<true, true,  1>, cudaFuncAttributeMaxDynamicSharedMemorySize, G2_SMEM);
    cudaFuncSetAttribute(hmma_gemm2<true, false, 0>, cudaFuncAttributeMaxDynamicSharedMemorySize, G2_SMEM);
    cudaFuncSetAttribute(hmma_av1, cudaFuncAttributeMaxDynamicSharedMemorySize, AV_SMEM);

    // Launches 1-5: prereqs of qk-proj only (so launch #6 = hmma_gemm3 for ncu)
    concat_bias_qk<<<2, 256>>>(bq, bk, bqk);                              // 1
    {
        dim3 blk(32, 8), grd(16, 16);
        transpose_split_w16<<<grd, blk>>>(Wq, wqks, 0);                   // 2
        transpose_split_w16<<<grd, blk>>>(Wk, wqks, 512);                 // 3
        split16_rows512<<<(BN_ROWS * 512 / 8) / 256, 256>>>(h, hs);       // 4
        transpose_plain_w16<<<grd, blk>>>(Wv, (__half*)wv16);             // 5
    }

    // 6) qk-proj: [32768,1024] = h @ wqk^T + bqk -> qk split (ldc 4096B)
    {
        dim3 grd(1024 / 128, BN_ROWS / 128, 1);
        hmma_gemm3<true, 1><<<grd, 256, G3_SMEM>>>(
            hs, wqks, bqk, nullptr, qks, 512, 2048, 2048, 4096, 0, 0, 0);
    }

    // remaining weight transposes (needed only by MLP)
    {
        dim3 blk(32, 8), grd(16, 16);
        transpose_plain_w16<<<grd, blk>>>(W1, (__half*)w116);
        transpose_plain_w16<<<grd, blk>>>(W2, (__half*)w216);
    }

    // v-proj + v^T
    {
        dim3 grd(512 / 128, BN_ROWS / 128, 1);
        hmma_gemm2<true, false, 2><<<grd, 256, G2_SMEM>>>(
            hs, wv16, bv, nullptr, v16, 512, 2048, 1024, 1024);
    }
    {
        dim3 blk(32, 8), grd(16, 64, BB);
        vt_transpose16<<<grd, blk>>>((const __half*)v16, (__half*)vt16);
    }

    // Attention middle, group-chained for L2 residency of att
    const long long sQK  = 2048LL * 4096;        // bytes per batch in qk split
    const long long sATTf = 2048LL * 2048;       // floats per batch
    for (int g = 0; g < BB / GRP; ++g) {
        const long long b0 = (long long)g * GRP;
        // logits: att[b] = q @ k^T (fp32 out)
        {
            dim3 grd(NSEQ / 128, NSEQ / 128, GRP);
            hmma_gemm3<false, 0><<<grd, 256, G3_SMEM>>>(
                qks + b0 * sQK, qks + b0 * sQK + 2048, nullptr,
                att + b0 * sATTf, nullptr,
                512, 4096, 4096, 8192,
                sQK, sQK, 2048LL * 8192);
        }
        // softmax -> att fp16
        softmax_f16_kernel<<<GRP * NSEQ, 256>>>(att + b0 * sATTf,
                                                atth + b0 * sATTf);
        // AV -> o split fp16
        {
            dim3 grd(512 / 128, NSEQ / 128, GRP);
            hmma_av1<<<grd, 256, AV_SMEM>>>(
                (const uint8_t*)(atth + b0 * sATTf),
                vt16 + b0 * 512LL * 4096,
                os + b0 * 2048LL * 2048);
        }
    }

    // MLP
    {
        dim3 grd(512 / 128, BN_ROWS / 128, 1);
        hmma_gemm2<true, true, 1><<<grd, 256, G2_SMEM>>>(
            os, w116, b1, nullptr, hids, 512, 2048, 1024, 2048);
        hmma_gemm2<true, false, 0><<<grd, 256, G2_SMEM>>>(
            hids, w216, b2, out, nullptr, 512, 2048, 1024, 2048);
    }
}

// round 11
// speedup vs baseline: 1.0657x; 1.0657x over previous
#include <cuda_runtime.h>
#include <cuda_fp16.h>
#include <math.h>
#include <stdint.h>

// Problem dims (fixed)
#define BB 16
#define NSEQ 2048
#define MM 512
#define HH 512
#define BN_ROWS (BB * NSEQ)   // 32768

// ---------------------------------------------------------------------------
// Split layout (fp16): for a logical [R x K] matrix, 4 bytes/elem as groups of
// 32 columns: each 128B group = 32 fp16 "hi" then 32 fp16 "lo".
// byte(r, c) = r*rowBytes + (c>>5)*128 + (c&31)*2   (hi; lo at +64)
// Plain fp16 layout: byte(r, c) = r*rowBytes + c*2.
// ---------------------------------------------------------------------------
__device__ __align__(128) uint8_t g_h_s  [(long long)BN_ROWS * HH * 4];     // h split
__device__ __align__(128) uint8_t g_qk_s [(long long)BN_ROWS * 1024 * 4];   // q|k split
__device__ __align__(128) uint8_t g_v16  [(long long)BN_ROWS * HH * 2];     // v plain
__device__ __align__(128) uint8_t g_vt16 [(long long)BN_ROWS * HH * 2];     // v^T plain
__device__ __align__(128) uint8_t g_o_s  [(long long)BN_ROWS * HH * 4];     // o split
__device__ __align__(128) uint8_t g_hid_s[(long long)BN_ROWS * HH * 4];     // hid split
__device__ __align__(128) uint8_t g_wqk_s[1024LL * 512 * 4];                // Wq^T|Wk^T split
__device__ __align__(128) uint8_t g_wv16 [512LL * 512 * 2];                 // Wv^T plain
__device__ __align__(128) uint8_t g_w116 [512LL * 512 * 2];                 // W1^T plain
__device__ __align__(128) uint8_t g_w216 [512LL * 512 * 2];                 // W2^T plain
__device__ float g_att[(long long)BB * NSEQ * NSEQ];
__device__ __align__(128) __half g_atth[(long long)BB * NSEQ * NSEQ];
__device__ float g_bqk[1024];

// ---------------------------------------------------------------------------
// Helpers
// ---------------------------------------------------------------------------
__device__ __forceinline__ uint32_t smem_u32(const void* p) {
    uint32_t a;
    asm("{ .reg .u64 t; cvta.to.shared.u64 t, %1; cvt.u32.u64 %0, t; }" : "=r"(a) : "l"(p));
    return a;
}
__device__ __forceinline__ void ldsm4(uint32_t* r, uint32_t addr) {
    asm volatile("ldmatrix.sync.aligned.m8n8.x4.shared.b16 {%0,%1,%2,%3}, [%4];"
                 : "=r"(r[0]), "=r"(r[1]), "=r"(r[2]), "=r"(r[3]) : "r"(addr));
}
__device__ __forceinline__ void mma_f16(float* c, const uint32_t* a,
                                        uint32_t b0, uint32_t b1) {
    asm volatile(
        "mma.sync.aligned.m16n8k16.row.col.f32.f16.f16.f32 "
        "{%0,%1,%2,%3}, {%4,%5,%6,%7}, {%8,%9}, {%0,%1,%2,%3};"
        : "+f"(c[0]), "+f"(c[1]), "+f"(c[2]), "+f"(c[3])
        : "r"(a[0]), "r"(a[1]), "r"(a[2]), "r"(a[3]), "r"(b0), "r"(b1));
}
__device__ __forceinline__ void cp16(uint32_t dst, const void* src) {
    asm volatile("cp.async.cg.shared.global [%0], [%1], 16;" :: "r"(dst), "l"(src));
}
__device__ __forceinline__ void cp_commit() {
    asm volatile("cp.async.commit_group;");
}
template <int N> __device__ __forceinline__ void cp_wait() {
    asm volatile("cp.async.wait_group %0;" :: "n"(N));
}
__device__ __forceinline__ void split2h(float x, float y, uint32_t& hi, uint32_t& lo) {
    __half2 h = __floats2half2_rn(x, y);
    __half2 l = __floats2half2_rn(x - __half2float(h.x), y - __half2float(h.y));
    hi = *(uint32_t*)&h;
    lo = *(uint32_t*)&l;
}

// Plain-fp16 smem tile addressing (64B of data per row, 2 rows packed per 128B
// line, 8-chunk XOR swizzle): conflict-free for ldmatrix and cp.async.
__device__ __forceinline__ uint32_t plainb_addr(uint32_t base, int r, int c) {
    return base + ((r >> 1) << 7) + (((((r & 1) << 2) + c) ^ ((r >> 1) & 7)) << 4);
}

// OUTMODE: 0 = fp32, 1 = split fp16, 2 = plain fp16

// ---------------------------------------------------------------------------
// gemm3: A split fp16, B split fp16, 3 MMAs (HH, HL, LH), chain-batched.
// CTA 128x128, warp 32x64, K staged 32, 3-deep cp.async, 2 CTAs/SM.
// ---------------------------------------------------------------------------
#define G3_STAGES 3
#define G3_STAGE 32768
#define G3_SMEM (G3_STAGES * G3_STAGE)

template <bool HAS_BIAS, int OUTMODE>
__global__ __launch_bounds__(256, 2)
void hmma_gemm3(const uint8_t* __restrict__ A, const uint8_t* __restrict__ B,
                const float* __restrict__ bias, float* __restrict__ Cf,
                uint8_t* __restrict__ Cs,
                int K, long long ldaB, long long ldbB, long long ldcB,
                long long sA, long long sB, long long sC)
{
    extern __shared__ uint8_t sm[];
    const long long bz = blockIdx.z;
    A += bz * sA;
    B += bz * sB;

    const int tid = threadIdx.x;
    const int wid = tid >> 5, lane = tid & 31;
    const int wm = wid & 3, wn = wid >> 2;
    const int lr = lane & 15, lc = lane >> 4;
    const int m0 = blockIdx.y * 128, n0 = blockIdx.x * 128;

    const int lrow = tid >> 1;
    const int cb = (tid & 1) * 4;
    const int rsw = lrow & 7;

    const uint32_t smb = smem_u32(sm);
    const uint8_t* srcA0 = A + (long long)(m0 + lrow) * ldaB + cb * 16;
    const uint8_t* srcB0 = B + (long long)(n0 + lrow) * ldbB + cb * 16;

    float acc[2][8][4];
#pragma unroll
    for (int i = 0; i < 2; ++i)
#pragma unroll
        for (int j = 0; j < 8; ++j)
#pragma unroll
            for (int t = 0; t < 4; ++t) acc[i][j][t] = 0.0f;

    const int S = K / 32;

#define G3_ISSUE(s)                                                           \
    do {                                                                      \
        const uint32_t dra = smb + ((s) % G3_STAGES) * G3_STAGE + lrow * 128; \
        const uint8_t* pa = srcA0 + (s) * 128;                                \
        const uint8_t* pb = srcB0 + (s) * 128;                                \
        _Pragma("unroll")                                                     \
        for (int c = 0; c < 4; ++c)                                           \
            cp16(dra + (((cb + c) ^ rsw) << 4), pa + c * 16);                 \
        _Pragma("unroll")                                                     \
        for (int c = 0; c < 4; ++c)                                           \
            cp16(dra + 16384 + (((cb + c) ^ rsw) << 4), pb + c * 16);         \
        cp_commit();                                                          \
    } while (0)

    G3_ISSUE(0);
    G3_ISSUE(1);

    for (int s = 0; s < S; ++s) {
        if (s + 1 < S) cp_wait<1>(); else cp_wait<0>();
        __syncthreads();
        if (s + 2 < S) G3_ISSUE(s + 2);

        const uint32_t bufA = smb + (s % G3_STAGES) * G3_STAGE;
        const uint32_t bufB = bufA + 16384;

#pragma unroll
        for (int kk = 0; kk < 2; ++kk) {
            uint32_t aH[2][4], aL[2][4];
            const int byteh = kk * 32 + lc * 16;
#pragma unroll
            for (int mi = 0; mi < 2; ++mi) {
                const int r = wm * 32 + mi * 16 + lr;
                const uint32_t rb = bufA + r * 128;
                const int rs = r & 7;
                ldsm4(aH[mi], rb + ((((byteh) >> 4) ^ rs) << 4));
                ldsm4(aL[mi], rb + ((((byteh + 64) >> 4) ^ rs) << 4));
            }
#pragma unroll
            for (int g = 0; g < 4; ++g) {
                const int r = wn * 64 + g * 16 + lr;
                const uint32_t rb = bufB + r * 128;
                const int rs = r & 7;
                uint32_t bh[4], bl[4];
                ldsm4(bh, rb + ((((byteh) >> 4) ^ rs) << 4));
                ldsm4(bl, rb + ((((byteh + 64) >> 4) ^ rs) << 4));
#pragma unroll
                for (int mi = 0; mi < 2; ++mi) {          // HH
                    mma_f16(acc[mi][2 * g],     aH[mi], bh[0], bh[2]);
                    mma_f16(acc[mi][2 * g + 1], aH[mi], bh[1], bh[3]);
                }
#pragma unroll
                for (int mi = 0; mi < 2; ++mi) {          // HL
                    mma_f16(acc[mi][2 * g],     aH[mi], bl[0], bl[2]);
                    mma_f16(acc[mi][2 * g + 1], aH[mi], bl[1], bl[3]);
                }
#pragma unroll
                for (int mi = 0; mi < 2; ++mi) {          // LH
                    mma_f16(acc[mi][2 * g],     aL[mi], bh[0], bh[2]);
                    mma_f16(acc[mi][2 * g + 1], aL[mi], bh[1], bh[3]);
                }
            }
        }
    }
#undef G3_ISSUE

#pragma unroll
    for (int mi = 0; mi < 2; ++mi) {
        const long long r0 = m0 + wm * 32 + mi * 16 + (lane >> 2);
#pragma unroll
        for (int nj = 0; nj < 8; ++nj) {
            const int col = n0 + wn * 64 + nj * 8 + 2 * (lane & 3);
            float bx = 0.0f, by = 0.0f;
            if (HAS_BIAS) {
                const float2 bvv = *(const float2*)(bias + col);
                bx = bvv.x; by = bvv.y;
            }
            const float x0 = acc[mi][nj][0] + bx;
            const float x1 = acc[mi][nj][1] + by;
            const float x2 = acc[mi][nj][2] + bx;
            const float x3 = acc[mi][nj][3] + by;
            if (OUTMODE == 0) {
                uint8_t* base = (uint8_t*)Cf + bz * sC;
                *(float2*)(base + r0 * ldcB + col * 4)       = make_float2(x0, x1);
                *(float2*)(base + (r0 + 8) * ldcB + col * 4) = make_float2(x2, x3);
            } else {
                uint8_t* base = Cs + bz * sC;
                const long long cb0 = (long long)(col >> 5) * 128 + (col & 31) * 2;
                uint32_t hi, lo;
                split2h(x0, x1, hi, lo);
                uint8_t* p = base + r0 * ldcB + cb0;
                *(uint32_t*)p = hi;
                *(uint32_t*)(p + 64) = lo;
                split2h(x2, x3, hi, lo);
                p = base + (r0 + 8) * ldcB + cb0;
                *(uint32_t*)p = hi;
                *(uint32_t*)(p + 64) = lo;
            }
        }
    }
}

// ---------------------------------------------------------------------------
// gemm2: A split fp16, B plain fp16 (single), 2 MMAs, chain-batched.
// 4-deep cp.async (96KB smem, 2 CTAs/SM).
// ---------------------------------------------------------------------------
#define G2_STAGES 4
#define G2_STAGE 24576
#define G2_SMEM (G2_STAGES * G2_STAGE)

template <bool HAS_BIAS, bool RELU, int OUTMODE>
__global__ __launch_bounds__(256, 2)
void hmma_gemm2(const uint8_t* __restrict__ A, const uint8_t* __restrict__ B,
                const float* __restrict__ bias, float* __restrict__ Cf,
                uint8_t* __restrict__ Cs,
                int K, long long ldaB, long long ldbB, long long ldcB)
{
    extern __shared__ uint8_t sm[];
    const int tid = threadIdx.x;
    const int wid = tid >> 5, lane = tid & 31;
    const int wm = wid & 3, wn = wid >> 2;
    const int lr = lane & 15, lc = lane >> 4;
    const int m0 = blockIdx.y * 128, n0 = blockIdx.x * 128;

    const int lrow = tid >> 1;
    const int cbA = (tid & 1) * 4;
    const int cbB = (tid & 1) * 2;
    const int rsw = lrow & 7;

    const uint32_t smb = smem_u32(sm);
    const uint8_t* srcA0 = A + (long long)(m0 + lrow) * ldaB + cbA * 16;
    const uint8_t* srcB0 = B + (long long)(n0 + lrow) * ldbB + cbB * 16;

    float acc[2][8][4];
#pragma unroll
    for (int i = 0; i < 2; ++i)
#pragma unroll
        for (int j = 0; j < 8; ++j)
#pragma unroll
            for (int t = 0; t < 4; ++t) acc[i][j][t] = 0.0f;

    const int S = K / 32;

#define G2_ISSUE(s)                                                           \
    do {                                                                      \
        const uint32_t stb = smb + ((s) % G2_STAGES) * G2_STAGE;              \
        const uint8_t* pa = srcA0 + (s) * 128;                                \
        const uint8_t* pb = srcB0 + (s) * 64;                                 \
        const uint32_t dra = stb + lrow * 128;                                \
        _Pragma("unroll")                                                     \
        for (int c = 0; c < 4; ++c)                                           \
            cp16(dra + (((cbA + c) ^ rsw) << 4), pa + c * 16);                \
        _Pragma("unroll")                                                     \
        for (int c = 0; c < 2; ++c)                                           \
            cp16(plainb_addr(stb + 16384, lrow, cbB + c), pb + c * 16);       \
        cp_commit();                                                          \
    } while (0)

    G2_ISSUE(0);
    G2_ISSUE(1);
    G2_ISSUE(2);

    for (int s = 0; s < S; ++s) {
        if (s + 1 < S) cp_wait<2>(); else cp_wait<0>();
        __syncthreads();
        if (s + 3 < S) G2_ISSUE(s + 3);

        const uint32_t bufA = smb + (s % G2_STAGES) * G2_STAGE;
        const uint32_t bufB = bufA + 16384;

#pragma unroll
        for (int kk = 0; kk < 2; ++kk) {
            uint32_t aH[2][4], aL[2][4];
            const int byteh = kk * 32 + lc * 16;
#pragma unroll
            for (int mi = 0; mi < 2; ++mi) {
                const int r = wm * 32 + mi * 16 + lr;
                const uint32_t rb = bufA + r * 128;
                const int rs = r & 7;
                ldsm4(aH[mi], rb + ((((byteh) >> 4) ^ rs) << 4));
                ldsm4(aL[mi], rb + ((((byteh + 64) >> 4) ^ rs) << 4));
            }
#pragma unroll
            for (int g = 0; g < 4; ++g) {
                const int r = wn * 64 + g * 16 + lr;
                const int c = kk * 2 + lc;
                uint32_t b[4];
                ldsm4(b, plainb_addr(bufB, r, c));
#pragma unroll
                for (int mi = 0; mi < 2; ++mi) {          // H*b
                    mma_f16(acc[mi][2 * g],     aH[mi], b[0], b[2]);
                    mma_f16(acc[mi][2 * g + 1], aH[mi], b[1], b[3]);
                }
#pragma unroll
                for (int mi = 0; mi < 2; ++mi) {          // L*b
                    mma_f16(acc[mi][2 * g],     aL[mi], b[0], b[2]);
                    mma_f16(acc[mi][2 * g + 1], aL[mi], b[1], b[3]);
                }
            }
        }
    }
#undef G2_ISSUE

#pragma unroll
    for (int mi = 0; mi < 2; ++mi) {
        const long long r0 = m0 + wm * 32 + mi * 16 + (lane >> 2);
#pragma unroll
        for (int nj = 0; nj < 8; ++nj) {
            const int col = n0 + wn * 64 + nj * 8 + 2 * (lane & 3);
            float bx = 0.0f, by = 0.0f;
            if (HAS_BIAS) {
                const float2 bvv = *(const float2*)(bias + col);
                bx = bvv.x; by = bvv.y;
            }
            float x0 = acc[mi][nj][0] + bx;
            float x1 = acc[mi][nj][1] + by;
            float x2 = acc[mi][nj][2] + bx;
            float x3 = acc[mi][nj][3] + by;
            if (RELU) {
                x0 = fmaxf(x0, 0.0f); x1 = fmaxf(x1, 0.0f);
                x2 = fmaxf(x2, 0.0f); x3 = fmaxf(x3, 0.0f);
            }
            if (OUTMODE == 0) {
                *(float2*)((uint8_t*)Cf + r0 * ldcB + col * 4)       = make_float2(x0, x1);
                *(float2*)((uint8_t*)Cf + (r0 + 8) * ldcB + col * 4) = make_float2(x2, x3);
            } else if (OUTMODE == 1) {
                const long long cb0 = (long long)(col >> 5) * 128 + (col & 31) * 2;
                uint32_t hi, lo;
                split2h(x0, x1, hi, lo);
                uint8_t* p = Cs + r0 * ldcB + cb0;
                *(uint32_t*)p = hi;
                *(uint32_t*)(p + 64) = lo;
                split2h(x2, x3, hi, lo);
                p = Cs + (r0 + 8) * ldcB + cb0;
                *(uint32_t*)p = hi;
                *(uint32_t*)(p + 64) = lo;
            } else {
                __half2 v01 = __floats2half2_rn(x0, x1);
                __half2 v23 = __floats2half2_rn(x2, x3);
                *(uint32_t*)(Cs + r0 * ldcB + col * 2)       = *(uint32_t*)&v01;
                *(uint32_t*)(Cs + (r0 + 8) * ldcB + col * 2) = *(uint32_t*)&v23;
            }
        }
    }
}

// ---------------------------------------------------------------------------
// av1: o[b] = att[b] @ vt[b]^T; both plain fp16, 1 MMA. 4-deep cp.async.
// ---------------------------------------------------------------------------
#define AV_STAGES 4
#define AV_STAGE 16384
#define AV_SMEM (AV_STAGES * AV_STAGE)

__global__ __launch_bounds__(256, 2)
void hmma_av1(const uint8_t* __restrict__ A, const uint8_t* __restrict__ B,
              uint8_t* __restrict__ Cs)
{
    extern __shared__ uint8_t sm[];
    const long long bz = blockIdx.z;
    A += bz * (long long)NSEQ * 4096;       // att rows, 2048 fp16
    B += bz * 512LL * 4096;                 // vt rows, 2048 fp16

    const int tid = threadIdx.x;
    const int wid = tid >> 5, lane = tid & 31;
    const int wm = wid & 3, wn = wid >> 2;
    const int lr = lane & 15, lc = lane >> 4;
    const int m0 = blockIdx.y * 128, n0 = blockIdx.x * 128;

    const int lrow = tid >> 1;
    const int cb2 = (tid & 1) * 2;

    const uint32_t smb = smem_u32(sm);
    const uint8_t* srcA0 = A + (long long)(m0 + lrow) * 4096 + cb2 * 16;
    const uint8_t* srcB0 = B + (long long)(n0 + lrow) * 4096 + cb2 * 16;

    float acc[2][8][4];
#pragma unroll
    for (int i = 0; i < 2; ++i)
#pragma unroll
        for (int j = 0; j < 8; ++j)
#pragma unroll
            for (int t = 0; t < 4; ++t) acc[i][j][t] = 0.0f;

    const int S = NSEQ / 32;  // 64

#define AV_ISSUE(s)                                                           \
    do {                                                                      \
        const uint32_t stb = smb + ((s) % AV_STAGES) * AV_STAGE;              \
        const uint8_t* pa = srcA0 + (s) * 64;                                 \
        const uint8_t* pb = srcB0 + (s) * 64;                                 \
        _Pragma("unroll")                                                     \
        for (int c = 0; c < 2; ++c)                                           \
            cp16(plainb_addr(stb, lrow, cb2 + c), pa + c * 16);               \
        _Pragma("unroll")                                                     \
        for (int c = 0; c < 2; ++c)                                           \
            cp16(plainb_addr(stb + 8192, lrow, cb2 + c), pb + c * 16);        \
        cp_commit();                                                          \
    } while (0)

    AV_ISSUE(0);
    AV_ISSUE(1);
    AV_ISSUE(2);

    for (int s = 0; s < S; ++s) {
        if (s + 1 < S) cp_wait<2>(); else cp_wait<0>();
        __syncthreads();
        if (s + 3 < S) AV_ISSUE(s + 3);

        const uint32_t bufA = smb + (s % AV_STAGES) * AV_STAGE;
        const uint32_t bufB = bufA + 8192;

#pragma unroll
        for (int kk = 0; kk < 2; ++kk) {
            const int c = kk * 2 + lc;
            uint32_t aF[2][4];
#pragma unroll
            for (int mi = 0; mi < 2; ++mi) {
                const int r = wm * 32 + mi * 16 + lr;
                ldsm4(aF[mi], plainb_addr(bufA, r, c));
            }
#pragma unroll
            for (int g = 0; g < 4; ++g) {
                const int r = wn * 64 + g * 16 + lr;
                uint32_t b[4];
                ldsm4(b, plainb_addr(bufB, r, c));
#pragma unroll
                for (int mi = 0; mi < 2; ++mi) {
                    mma_f16(acc[mi][2 * g],     aF[mi], b[0], b[2]);
                    mma_f16(acc[mi][2 * g + 1], aF[mi], b[1], b[3]);
                }
            }
        }
    }
#undef AV_ISSUE

#pragma unroll
    for (int mi = 0; mi < 2; ++mi) {
        const long long r0 = bz * NSEQ + m0 + wm * 32 + mi * 16 + (lane >> 2);
#pragma unroll
        for (int nj = 0; nj < 8; ++nj) {
            const int col = n0 + wn * 64 + nj * 8 + 2 * (lane & 3);
            const long long cb0 = (long long)(col >> 5) * 128 + (col & 31) * 2;
            uint32_t hi, lo;
            split2h(acc[mi][nj][0], acc[mi][nj][1], hi, lo);
            uint8_t* p = Cs + r0 * 2048 + cb0;
            *(uint32_t*)p = hi;
            *(uint32_t*)(p + 64) = lo;
            split2h(acc[mi][nj][2], acc[mi][nj][3], hi, lo);
            p = Cs + (r0 + 8) * 2048 + cb0;
            *(uint32_t*)p = hi;
            *(uint32_t*)(p + 64) = lo;
        }
    }
}

// ---------------------------------------------------------------------------
// Prep kernels
// ---------------------------------------------------------------------------
__global__ __launch_bounds__(256)
void split16_rows512(const float* __restrict__ in, uint8_t* __restrict__ out)
{
    const long long i8 = ((long long)blockIdx.x * 256 + threadIdx.x) * 8;
    const long long row = i8 >> 9;
    const int col = (int)(i8 & 511);
    const float4 a = *(const float4*)(in + i8);
    const float4 b = *(const float4*)(in + i8 + 4);
    uint4 hi, lo;
    split2h(a.x, a.y, hi.x, lo.x);
    split2h(a.z, a.w, hi.y, lo.y);
    split2h(b.x, b.y, hi.z, lo.z);
    split2h(b.z, b.w, hi.w, lo.w);
    uint8_t* p = out + row * 2048 + (col >> 5) * 128 + (col & 31) * 2;
    *(uint4*)p = hi;
    *(uint4*)(p + 64) = lo;
}

__global__ __launch_bounds__(256)
void transpose_split_w16(const float* __restrict__ in, uint8_t* __restrict__ out,
                         long long rowOff)
{
    __shared__ float t[32][33];
    const int c0 = blockIdx.x * 32;
    const int r0 = blockIdx.y * 32;
    const int x = threadIdx.x;
    const int y = threadIdx.y;
#pragma unroll
    for (int j = 0; j < 32; j += 8)
        t[y + j][x] = in[(long long)(r0 + y + j) * 512 + c0 + x];
    __syncthreads();
#pragma unroll
    for (int j = 0; j < 32; j += 8) {
        const float val = t[x][y + j];
        const long long row = rowOff + c0 + y + j;
        const int col = r0 + x;
        __half hi = __float2half_rn(val);
        __half lo = __float2half_rn(val - __half2float(hi));
        uint8_t* p = out + row * 2048 + (col >> 5) * 128 + (col & 31) * 2;
        *(__half*)p = hi;
        *(__half*)(p + 64) = lo;
    }
}

__global__ __launch_bounds__(256)
void transpose_plain_w16(const float* __restrict__ in, __half* __restrict__ out)
{
    __shared__ float t[32][33];
    const int c0 = blockIdx.x * 32;
    const int r0 = blockIdx.y * 32;
    const int x = threadIdx.x;
    const int y = threadIdx.y;
#pragma unroll
    for (int j = 0; j < 32; j += 8)
        t[y + j][x] = in[(long long)(r0 + y + j) * 512 + c0 + x];
    __syncthreads();
#pragma unroll
    for (int j = 0; j < 32; j += 8)
        out[(long long)(c0 + y + j) * 512 + r0 + x] = __float2half_rn(t[x][y + j]);
}

__global__ __launch_bounds__(256)
void vt_transpose16(const __half* __restrict__ v, __half* __restrict__ vt)
{
    __shared__ __half t[32][33];
    const long long b = blockIdx.z;
    const int h0 = blockIdx.x * 32;
    const int n0 = blockIdx.y * 32;
    const int x = threadIdx.x;
    const int y = threadIdx.y;
#pragma unroll
    for (int j = 0; j < 32; j += 8)
        t[y + j][x] = v[(b * 2048 + n0 + y + j) * 512 + h0 + x];
    __syncthreads();
#pragma unroll
    for (int j = 0; j < 32; j += 8)
        vt[b * 512 * 2048 + (long long)(h0 + y + j) * 2048 + n0 + x] = t[x][y + j];
}

// ---------------------------------------------------------------------------
// Row softmax (2048) fp32 -> fp16, threshold-gated exp (bit-equivalent output).
// ---------------------------------------------------------------------------
__global__ __launch_bounds__(256)
void softmax_f16_kernel(const float* __restrict__ att, __half* __restrict__ outh)
{
    const float* row = att + (long long)blockIdx.x * NSEQ;
    __half* orow = outh + (long long)blockIdx.x * NSEQ;
    __shared__ float sred[8];
    const int tid = threadIdx.x;
    const int wid = tid >> 5;
    const int lane = tid & 31;
    const int c0 = tid * 8;

    float r[8];
    *(float4*)&r[0] = *(const float4*)(row + c0);
    *(float4*)&r[4] = *(const float4*)(row + c0 + 4);

    float lmax = r[0];
#pragma unroll
    for (int p = 1; p < 8; ++p) lmax = fmaxf(lmax, r[p]);
    float m = lmax;
#pragma unroll
    for (int off = 16; off > 0; off >>= 1)
        m = fmaxf(m, __shfl_xor_sync(0xFFFFFFFFu, m, off));
    if (lane == 0) sred[wid] = m;
    __syncthreads();
    float M = sred[0];
#pragma unroll
    for (int w = 1; w < 8; ++w) M = fmaxf(M, sred[w]);

    float sum = 0.0f;
    if (lmax - M > -25.0f) {
#pragma unroll
        for (int p = 0; p < 8; ++p) {
            r[p] = __expf(r[p] - M);
            sum += r[p];
        }
    } else {
#pragma unroll
        for (int p = 0; p < 8; ++p) r[p] = 0.0f;
    }

#pragma unroll
    for (int off = 16; off > 0; off >>= 1)
        sum += __shfl_xor_sync(0xFFFFFFFFu, sum, off);
    __syncthreads();
    if (lane == 0) sred[wid] = sum;
    __syncthreads();
    float S = sred[0];
#pragma unroll
    for (int w = 1; w < 8; ++w) S += sred[w];
    const float inv = 1.0f / S;

    __half2 hh[4];
#pragma unroll
    for (int p = 0; p < 4; ++p)
        hh[p] = __floats2half2_rn(r[2 * p] * inv, r[2 * p + 1] * inv);
    *(uint4*)(orow + c0) = *(uint4*)hh;
}

__global__ void concat_bias_qk(const float* bq, const float* bk, float* dst)
{
    const int t = blockIdx.x * 256 + threadIdx.x;
    if (t < 512) {
        dst[t] = bq[t];
        dst[512 + t] = bk[t];
    }
}

// ---------------------------------------------------------------------------
// Launch. Round-9 batched structure + capture-legal stream fork/join:
//   s1 runs the v-chain and W1/W2 transposes under qk-proj/logits, and
//   softmax(H0)+AV(H0) under logits(H1)/softmax(H1).
// ---------------------------------------------------------------------------
extern "C" void kernel_launch(void* const* d_in, const int* in_sizes, int n_in,
                              void* d_out, int out_size)
{
    (void)in_sizes; (void)n_in; (void)out_size;
    const float* h  = (const float*)d_in[1];
    const float* Wv = (const float*)d_in[2];
    const float* bv = (const float*)d_in[3];
    const float* Wk = (const float*)d_in[4];
    const float* bk = (const float*)d_in[5];
    const float* Wq = (const float*)d_in[6];
    const float* bq = (const float*)d_in[7];
    const float* W1 = (const float*)d_in[8];
    const float* b1 = (const float*)d_in[9];
    const float* W2 = (const float*)d_in[10];
    const float* b2 = (const float*)d_in[11];
    float* out = (float*)d_out;

    uint8_t *hs, *qks, *v16, *vt16, *os, *hids, *wqks, *wv16, *w116, *w216;
    float *att, *bqk;
    __half* atth;
    cudaGetSymbolAddress((void**)&hs,   g_h_s);
    cudaGetSymbolAddress((void**)&qks,  g_qk_s);
    cudaGetSymbolAddress((void**)&v16,  g_v16);
    cudaGetSymbolAddress((void**)&vt16, g_vt16);
    cudaGetSymbolAddress((void**)&os,   g_o_s);
    cudaGetSymbolAddress((void**)&hids, g_hid_s);
    cudaGetSymbolAddress((void**)&wqks, g_wqk_s);
    cudaGetSymbolAddress((void**)&wv16, g_wv16);
    cudaGetSymbolAddress((void**)&w116, g_w116);
    cudaGetSymbolAddress((void**)&w216, g_w216);
    cudaGetSymbolAddress((void**)&att,  g_att);
    cudaGetSymbolAddress((void**)&atth, g_atth);
    cudaGetSymbolAddress((void**)&bqk,  g_bqk);

    static cudaStream_t s1 = nullptr;
    static cudaEvent_t evFork = nullptr, evLog0 = nullptr, evJoin = nullptr;
    if (!s1) {
        cudaStreamCreateWithFlags(&s1, cudaStreamNonBlocking);
        cudaEventCreateWithFlags(&evFork, cudaEventDisableTiming);
        cudaEventCreateWithFlags(&evLog0, cudaEventDisableTiming);
        cudaEventCreateWithFlags(&evJoin, cudaEventDisableTiming);
    }

    cudaFuncSetAttribute(hmma_gemm3<true,  1>, cudaFuncAttributeMaxDynamicSharedMemorySize, G3_SMEM);
    cudaFuncSetAttribute(hmma_gemm3<false, 0>, cudaFuncAttributeMaxDynamicSharedMemorySize, G3_SMEM);
    cudaFuncSetAttribute(hmma_gemm2<true, false, 2>, cudaFuncAttributeMaxDynamicSharedMemorySize, G2_SMEM);
    cudaFuncSetAttribute(hmma_gemm2<true, true,  1>, cudaFuncAttributeMaxDynamicSharedMemorySize, G2_SMEM);
    cudaFuncSetAttribute(hmma_gemm2<true, false, 0>, cudaFuncAttributeMaxDynamicSharedMemorySize, G2_SMEM);
    cudaFuncSetAttribute(hmma_av1, cudaFuncAttributeMaxDynamicSharedMemorySize, AV_SMEM);

    const dim3 tblk(32, 8), tgrd(16, 16);
    const long long sQK   = 2048LL * 4096;   // bytes per batch in qk split
    const long long sATTf = 2048LL * 2048;   // floats per batch of att
    const int HB = BB / 2;                   // half-batch

    // ---- main stream: qk path prereqs ----
    concat_bias_qk<<<2, 256>>>(bq, bk, bqk);
    transpose_split_w16<<<tgrd, tblk>>>(Wq, wqks, 0);
    transpose_split_w16<<<tgrd, tblk>>>(Wk, wqks, 512);
    split16_rows512<<<(BN_ROWS * 512 / 8) / 256, 256>>>(h, hs);

    // ---- fork s1: v-chain + MLP weight transposes (independent of qk path) ----
    cudaEventRecord(evFork, 0);
    cudaStreamWaitEvent(s1, evFork, 0);
    transpose_plain_w16<<<tgrd, tblk, 0, s1>>>(Wv, (__half*)wv16);
    transpose_plain_w16<<<tgrd, tblk, 0, s1>>>(W1, (__half*)w116);
    transpose_plain_w16<<<tgrd, tblk, 0, s1>>>(W2, (__half*)w216);
    {
        dim3 grd(512 / 128, BN_ROWS / 128, 1);
        hmma_gemm2<true, false, 2><<<grd, 256, G2_SMEM, s1>>>(
            hs, wv16, bv, nullptr, v16, 512, 2048, 1024, 1024);
    }
    {
        dim3 blk(32, 8), grd(16, 64, BB);
        vt_transpose16<<<grd, blk, 0, s1>>>((const __half*)v16, (__half*)vt16);
    }

    // ---- main: qk-proj, then logits(H0) ----
    {
        dim3 grd(1024 / 128, BN_ROWS / 128, 1);
        hmma_gemm3<true, 1><<<grd, 256, G3_SMEM>>>(
            hs, wqks, bqk, nullptr, qks, 512, 2048, 2048, 4096, 0, 0, 0);
    }
    {
        dim3 grd(NSEQ / 128, NSEQ / 128, HB);
        hmma_gemm3<false, 0><<<grd, 256, G3_SMEM>>>(
            qks, qks + 2048, nullptr, att, nullptr,
            512, 4096, 4096, 8192, sQK, sQK, 2048LL * 8192);
    }
    cudaEventRecord(evLog0, 0);

    // ---- s1: softmax(H0) + AV(H0), overlapping logits(H1)/softmax(H1) ----
    cudaStreamWaitEvent(s1, evLog0, 0);
    softmax_f16_kernel<<<HB * NSEQ, 256, 0, s1>>>(att, atth);
    {
        dim3 grd(512 / 128, NSEQ / 128, HB);
        hmma_av1<<<grd, 256, AV_SMEM, s1>>>((const uint8_t*)atth, vt16, os);
    }
    cudaEventRecord(evJoin, s1);

    // ---- main: logits(H1), softmax(H1), AV(H1) ----
    {
        dim3 grd(NSEQ / 128, NSEQ / 128, HB);
        hmma_gemm3<false, 0><<<grd, 256, G3_SMEM>>>(
            qks + HB * sQK, qks + HB * sQK + 2048, nullptr,
            att + HB * sATTf, nullptr,
            512, 4096, 4096, 8192, sQK, sQK, 2048LL * 8192);
    }
    softmax_f16_kernel<<<HB * NSEQ, 256>>>(att + HB * sATTf, atth + HB * sATTf);
    cudaStreamWaitEvent(0, evJoin, 0);   // join: vt + AV(H0) complete
    {
        dim3 grd(512 / 128, NSEQ / 128, HB);
        hmma_av1<<<grd, 256, AV_SMEM>>>(
            (const uint8_t*)(atth + HB * sATTf),
            vt16 + (long long)HB * 512 * 4096,
            os + (long long)HB * 2048 * 2048);
    }

    // ---- MLP ----
    {
        dim3 grd(512 / 128, BN_ROWS / 128, 1);
        hmma_gemm2<true, true, 1><<<grd, 256, G2_SMEM>>>(
            os, w116, b1, nullptr, hids, 512, 2048, 1024, 2048);
        hmma_gemm2<true, false, 0><<<grd, 256, G2_SMEM>>>(
            hids, w216, b2, out, nullptr, 512, 2048, 1024, 2048);
    }
}

// round 12
// speedup vs baseline: 1.1068x; 1.0386x over previous
#include <cuda_runtime.h>
#include <cuda_fp16.h>
#include <math.h>
#include <stdint.h>

// Problem dims (fixed)
#define BB 16
#define NSEQ 2048
#define MM 512
#define HH 512
#define BN_ROWS (BB * NSEQ)   // 32768

// ---------------------------------------------------------------------------
// Split layout (fp16): for a logical [R x K] matrix, 4 bytes/elem as groups of
// 32 columns: each 128B group = 32 fp16 "hi" then 32 fp16 "lo".
// byte(r, c) = r*rowBytes + (c>>5)*128 + (c&31)*2   (hi; lo at +64)
// Plain fp16 layout: byte(r, c) = r*rowBytes + c*2.
// ---------------------------------------------------------------------------
__device__ __align__(128) uint8_t g_h_s  [(long long)BN_ROWS * HH * 4];     // h split
__device__ __align__(128) uint8_t g_t_s  [(long long)BN_ROWS * HH * 4];     // t = h@M split
__device__ __align__(128) uint8_t g_v16  [(long long)BN_ROWS * HH * 2];     // v plain
__device__ __align__(128) uint8_t g_vt16 [(long long)BN_ROWS * HH * 2];     // v^T plain
__device__ __align__(128) uint8_t g_o_s  [(long long)BN_ROWS * HH * 4];     // o split
__device__ __align__(128) uint8_t g_hid_s[(long long)BN_ROWS * HH * 4];     // hid split
__device__ __align__(128) uint8_t g_wm_s [512LL * 512 * 4];                 // M^T = Wk@Wq^T split
__device__ __align__(128) uint8_t g_wv16 [512LL * 512 * 2];                 // Wv^T plain
__device__ __align__(128) uint8_t g_w116 [512LL * 512 * 2];                 // W1^T plain
__device__ __align__(128) uint8_t g_w216 [512LL * 512 * 2];                 // W2^T plain
__device__ float g_att[(long long)BB * NSEQ * NSEQ];
__device__ __align__(128) __half g_atth[(long long)BB * NSEQ * NSEQ];
__device__ float g_u[512];            // Wk @ bq
__device__ float g_c[BN_ROWS];        // per-column softmax bias c_j = h_j . u

// ---------------------------------------------------------------------------
// Helpers
// ---------------------------------------------------------------------------
__device__ __forceinline__ uint32_t smem_u32(const void* p) {
    uint32_t a;
    asm("{ .reg .u64 t; cvta.to.shared.u64 t, %1; cvt.u32.u64 %0, t; }" : "=r"(a) : "l"(p));
    return a;
}
__device__ __forceinline__ void ldsm4(uint32_t* r, uint32_t addr) {
    asm volatile("ldmatrix.sync.aligned.m8n8.x4.shared.b16 {%0,%1,%2,%3}, [%4];"
                 : "=r"(r[0]), "=r"(r[1]), "=r"(r[2]), "=r"(r[3]) : "r"(addr));
}
__device__ __forceinline__ void mma_f16(float* c, const uint32_t* a,
                                        uint32_t b0, uint32_t b1) {
    asm volatile(
        "mma.sync.aligned.m16n8k16.row.col.f32.f16.f16.f32 "
        "{%0,%1,%2,%3}, {%4,%5,%6,%7}, {%8,%9}, {%0,%1,%2,%3};"
        : "+f"(c[0]), "+f"(c[1]), "+f"(c[2]), "+f"(c[3])
        : "r"(a[0]), "r"(a[1]), "r"(a[2]), "r"(a[3]), "r"(b0), "r"(b1));
}
__device__ __forceinline__ void cp16(uint32_t dst, const void* src) {
    asm volatile("cp.async.cg.shared.global [%0], [%1], 16;" :: "r"(dst), "l"(src));
}
__device__ __forceinline__ void cp_commit() {
    asm volatile("cp.async.commit_group;");
}
template <int N> __device__ __forceinline__ void cp_wait() {
    asm volatile("cp.async.wait_group %0;" :: "n"(N));
}
__device__ __forceinline__ void split2h(float x, float y, uint32_t& hi, uint32_t& lo) {
    __half2 h = __floats2half2_rn(x, y);
    __half2 l = __floats2half2_rn(x - __half2float(h.x), y - __half2float(h.y));
    hi = *(uint32_t*)&h;
    lo = *(uint32_t*)&l;
}

// Plain-fp16 smem tile addressing (64B of data per row, 2 rows packed per 128B
// line, 8-chunk XOR swizzle): conflict-free for ldmatrix and cp.async.
__device__ __forceinline__ uint32_t plainb_addr(uint32_t base, int r, int c) {
    return base + ((r >> 1) << 7) + (((((r & 1) << 2) + c) ^ ((r >> 1) & 7)) << 4);
}

// OUTMODE: 0 = fp32, 1 = split fp16, 2 = plain fp16

// ---------------------------------------------------------------------------
// gemm3: A split fp16, B split fp16, 3 MMAs (HH, HL, LH), chain-batched.
// CTA 128x128, warp 32x64, K staged 32, 3-deep cp.async, 2 CTAs/SM.
// ---------------------------------------------------------------------------
#define G3_STAGES 3
#define G3_STAGE 32768
#define G3_SMEM (G3_STAGES * G3_STAGE)

template <bool HAS_BIAS, int OUTMODE>
__global__ __launch_bounds__(256, 2)
void hmma_gemm3(const uint8_t* __restrict__ A, const uint8_t* __restrict__ B,
                const float* __restrict__ bias, float* __restrict__ Cf,
                uint8_t* __restrict__ Cs,
                int K, long long ldaB, long long ldbB, long long ldcB,
                long long sA, long long sB, long long sC)
{
    extern __shared__ uint8_t sm[];
    const long long bz = blockIdx.z;
    A += bz * sA;
    B += bz * sB;

    const int tid = threadIdx.x;
    const int wid = tid >> 5, lane = tid & 31;
    const int wm = wid & 3, wn = wid >> 2;
    const int lr = lane & 15, lc = lane >> 4;
    const int m0 = blockIdx.y * 128, n0 = blockIdx.x * 128;

    const int lrow = tid >> 1;
    const int cb = (tid & 1) * 4;
    const int rsw = lrow & 7;

    const uint32_t smb = smem_u32(sm);
    const uint8_t* srcA0 = A + (long long)(m0 + lrow) * ldaB + cb * 16;
    const uint8_t* srcB0 = B + (long long)(n0 + lrow) * ldbB + cb * 16;

    float acc[2][8][4];
#pragma unroll
    for (int i = 0; i < 2; ++i)
#pragma unroll
        for (int j = 0; j < 8; ++j)
#pragma unroll
            for (int t = 0; t < 4; ++t) acc[i][j][t] = 0.0f;

    const int S = K / 32;

#define G3_ISSUE(s)                                                           \
    do {                                                                      \
        const uint32_t dra = smb + ((s) % G3_STAGES) * G3_STAGE + lrow * 128; \
        const uint8_t* pa = srcA0 + (s) * 128;                                \
        const uint8_t* pb = srcB0 + (s) * 128;                                \
        _Pragma("unroll")                                                     \
        for (int c = 0; c < 4; ++c)                                           \
            cp16(dra + (((cb + c) ^ rsw) << 4), pa + c * 16);                 \
        _Pragma("unroll")                                                     \
        for (int c = 0; c < 4; ++c)                                           \
            cp16(dra + 16384 + (((cb + c) ^ rsw) << 4), pb + c * 16);         \
        cp_commit();                                                          \
    } while (0)

    G3_ISSUE(0);
    G3_ISSUE(1);

    for (int s = 0; s < S; ++s) {
        if (s + 1 < S) cp_wait<1>(); else cp_wait<0>();
        __syncthreads();
        if (s + 2 < S) G3_ISSUE(s + 2);

        const uint32_t bufA = smb + (s % G3_STAGES) * G3_STAGE;
        const uint32_t bufB = bufA + 16384;

#pragma unroll
        for (int kk = 0; kk < 2; ++kk) {
            uint32_t aH[2][4], aL[2][4];
            const int byteh = kk * 32 + lc * 16;
#pragma unroll
            for (int mi = 0; mi < 2; ++mi) {
                const int r = wm * 32 + mi * 16 + lr;
                const uint32_t rb = bufA + r * 128;
                const int rs = r & 7;
                ldsm4(aH[mi], rb + ((((byteh) >> 4) ^ rs) << 4));
                ldsm4(aL[mi], rb + ((((byteh + 64) >> 4) ^ rs) << 4));
            }
#pragma unroll
            for (int g = 0; g < 4; ++g) {
                const int r = wn * 64 + g * 16 + lr;
                const uint32_t rb = bufB + r * 128;
                const int rs = r & 7;
                uint32_t bh[4], bl[4];
                ldsm4(bh, rb + ((((byteh) >> 4) ^ rs) << 4));
                ldsm4(bl, rb + ((((byteh + 64) >> 4) ^ rs) << 4));
#pragma unroll
                for (int mi = 0; mi < 2; ++mi) {          // HH
                    mma_f16(acc[mi][2 * g],     aH[mi], bh[0], bh[2]);
                    mma_f16(acc[mi][2 * g + 1], aH[mi], bh[1], bh[3]);
                }
#pragma unroll
                for (int mi = 0; mi < 2; ++mi) {          // HL
                    mma_f16(acc[mi][2 * g],     aH[mi], bl[0], bl[2]);
                    mma_f16(acc[mi][2 * g + 1], aH[mi], bl[1], bl[3]);
                }
#pragma unroll
                for (int mi = 0; mi < 2; ++mi) {          // LH
                    mma_f16(acc[mi][2 * g],     aL[mi], bh[0], bh[2]);
                    mma_f16(acc[mi][2 * g + 1], aL[mi], bh[1], bh[3]);
                }
            }
        }
    }
#undef G3_ISSUE

#pragma unroll
    for (int mi = 0; mi < 2; ++mi) {
        const long long r0 = m0 + wm * 32 + mi * 16 + (lane >> 2);
#pragma unroll
        for (int nj = 0; nj < 8; ++nj) {
            const int col = n0 + wn * 64 + nj * 8 + 2 * (lane & 3);
            float bx = 0.0f, by = 0.0f;
            if (HAS_BIAS) {
                const float2 bvv = *(const float2*)(bias + col);
                bx = bvv.x; by = bvv.y;
            }
            const float x0 = acc[mi][nj][0] + bx;
            const float x1 = acc[mi][nj][1] + by;
            const float x2 = acc[mi][nj][2] + bx;
            const float x3 = acc[mi][nj][3] + by;
            if (OUTMODE == 0) {
                uint8_t* base = (uint8_t*)Cf + bz * sC;
                *(float2*)(base + r0 * ldcB + col * 4)       = make_float2(x0, x1);
                *(float2*)(base + (r0 + 8) * ldcB + col * 4) = make_float2(x2, x3);
            } else {
                uint8_t* base = Cs + bz * sC;
                const long long cb0 = (long long)(col >> 5) * 128 + (col & 31) * 2;
                uint32_t hi, lo;
                split2h(x0, x1, hi, lo);
                uint8_t* p = base + r0 * ldcB + cb0;
                *(uint32_t*)p = hi;
                *(uint32_t*)(p + 64) = lo;
                split2h(x2, x3, hi, lo);
                p = base + (r0 + 8) * ldcB + cb0;
                *(uint32_t*)p = hi;
                *(uint32_t*)(p + 64) = lo;
            }
        }
    }
}

// ---------------------------------------------------------------------------
// gemm2: A split fp16, B plain fp16 (single), 2 MMAs, chain-batched.
// 4-deep cp.async (96KB smem, 2 CTAs/SM).
// ---------------------------------------------------------------------------
#define G2_STAGES 4
#define G2_STAGE 24576
#define G2_SMEM (G2_STAGES * G2_STAGE)

template <bool HAS_BIAS, bool RELU, int OUTMODE>
__global__ __launch_bounds__(256, 2)
void hmma_gemm2(const uint8_t* __restrict__ A, const uint8_t* __restrict__ B,
                const float* __restrict__ bias, float* __restrict__ Cf,
                uint8_t* __restrict__ Cs,
                int K, long long ldaB, long long ldbB, long long ldcB)
{
    extern __shared__ uint8_t sm[];
    const int tid = threadIdx.x;
    const int wid = tid >> 5, lane = tid & 31;
    const int wm = wid & 3, wn = wid >> 2;
    const int lr = lane & 15, lc = lane >> 4;
    const int m0 = blockIdx.y * 128, n0 = blockIdx.x * 128;

    const int lrow = tid >> 1;
    const int cbA = (tid & 1) * 4;
    const int cbB = (tid & 1) * 2;
    const int rsw = lrow & 7;

    const uint32_t smb = smem_u32(sm);
    const uint8_t* srcA0 = A + (long long)(m0 + lrow) * ldaB + cbA * 16;
    const uint8_t* srcB0 = B + (long long)(n0 + lrow) * ldbB + cbB * 16;

    float acc[2][8][4];
#pragma unroll
    for (int i = 0; i < 2; ++i)
#pragma unroll
        for (int j = 0; j < 8; ++j)
#pragma unroll
            for (int t = 0; t < 4; ++t) acc[i][j][t] = 0.0f;

    const int S = K / 32;

#define G2_ISSUE(s)                                                           \
    do {                                                                      \
        const uint32_t stb = smb + ((s) % G2_STAGES) * G2_STAGE;              \
        const uint8_t* pa = srcA0 + (s) * 128;                                \
        const uint8_t* pb = srcB0 + (s) * 64;                                 \
        const uint32_t dra = stb + lrow * 128;                                \
        _Pragma("unroll")                                                     \
        for (int c = 0; c < 4; ++c)                                           \
            cp16(dra + (((cbA + c) ^ rsw) << 4), pa + c * 16);                \
        _Pragma("unroll")                                                     \
        for (int c = 0; c < 2; ++c)                                           \
            cp16(plainb_addr(stb + 16384, lrow, cbB + c), pb + c * 16);       \
        cp_commit();                                                          \
    } while (0)

    G2_ISSUE(0);
    G2_ISSUE(1);
    G2_ISSUE(2);

    for (int s = 0; s < S; ++s) {
        if (s + 1 < S) cp_wait<2>(); else cp_wait<0>();
        __syncthreads();
        if (s + 3 < S) G2_ISSUE(s + 3);

        const uint32_t bufA = smb + (s % G2_STAGES) * G2_STAGE;
        const uint32_t bufB = bufA + 16384;

#pragma unroll
        for (int kk = 0; kk < 2; ++kk) {
            uint32_t aH[2][4], aL[2][4];
            const int byteh = kk * 32 + lc * 16;
#pragma unroll
            for (int mi = 0; mi < 2; ++mi) {
                const int r = wm * 32 + mi * 16 + lr;
                const uint32_t rb = bufA + r * 128;
                const int rs = r & 7;
                ldsm4(aH[mi], rb + ((((byteh) >> 4) ^ rs) << 4));
                ldsm4(aL[mi], rb + ((((byteh + 64) >> 4) ^ rs) << 4));
            }
#pragma unroll
            for (int g = 0; g < 4; ++g) {
                const int r = wn * 64 + g * 16 + lr;
                const int c = kk * 2 + lc;
                uint32_t b[4];
                ldsm4(b, plainb_addr(bufB, r, c));
#pragma unroll
                for (int mi = 0; mi < 2; ++mi) {          // H*b
                    mma_f16(acc[mi][2 * g],     aH[mi], b[0], b[2]);
                    mma_f16(acc[mi][2 * g + 1], aH[mi], b[1], b[3]);
                }
#pragma unroll
                for (int mi = 0; mi < 2; ++mi) {          // L*b
                    mma_f16(acc[mi][2 * g],     aL[mi], b[0], b[2]);
                    mma_f16(acc[mi][2 * g + 1], aL[mi], b[1], b[3]);
                }
            }
        }
    }
#undef G2_ISSUE

#pragma unroll
    for (int mi = 0; mi < 2; ++mi) {
        const long long r0 = m0 + wm * 32 + mi * 16 + (lane >> 2);
#pragma unroll
        for (int nj = 0; nj < 8; ++nj) {
            const int col = n0 + wn * 64 + nj * 8 + 2 * (lane & 3);
            float bx = 0.0f, by = 0.0f;
            if (HAS_BIAS) {
                const float2 bvv = *(const float2*)(bias + col);
                bx = bvv.x; by = bvv.y;
            }
            float x0 = acc[mi][nj][0] + bx;
            float x1 = acc[mi][nj][1] + by;
            float x2 = acc[mi][nj][2] + bx;
            float x3 = acc[mi][nj][3] + by;
            if (RELU) {
                x0 = fmaxf(x0, 0.0f); x1 = fmaxf(x1, 0.0f);
                x2 = fmaxf(x2, 0.0f); x3 = fmaxf(x3, 0.0f);
            }
            if (OUTMODE == 0) {
                *(float2*)((uint8_t*)Cf + r0 * ldcB + col * 4)       = make_float2(x0, x1);
                *(float2*)((uint8_t*)Cf + (r0 + 8) * ldcB + col * 4) = make_float2(x2, x3);
            } else if (OUTMODE == 1) {
                const long long cb0 = (long long)(col >> 5) * 128 + (col & 31) * 2;
                uint32_t hi, lo;
                split2h(x0, x1, hi, lo);
                uint8_t* p = Cs + r0 * ldcB + cb0;
                *(uint32_t*)p = hi;
                *(uint32_t*)(p + 64) = lo;
                split2h(x2, x3, hi, lo);
                p = Cs + (r0 + 8) * ldcB + cb0;
                *(uint32_t*)p = hi;
                *(uint32_t*)(p + 64) = lo;
            } else {
                __half2 v01 = __floats2half2_rn(x0, x1);
                __half2 v23 = __floats2half2_rn(x2, x3);
                *(uint32_t*)(Cs + r0 * ldcB + col * 2)       = *(uint32_t*)&v01;
                *(uint32_t*)(Cs + (r0 + 8) * ldcB + col * 2) = *(uint32_t*)&v23;
            }
        }
    }
}

// ---------------------------------------------------------------------------
// av1: o[b] = att[b] @ vt[b]^T; both plain fp16, 1 MMA. 4-deep cp.async.
// ---------------------------------------------------------------------------
#define AV_STAGES 4
#define AV_STAGE 16384
#define AV_SMEM (AV_STAGES * AV_STAGE)

__global__ __launch_bounds__(256, 2)
void hmma_av1(const uint8_t* __restrict__ A, const uint8_t* __restrict__ B,
              uint8_t* __restrict__ Cs)
{
    extern __shared__ uint8_t sm[];
    const long long bz = blockIdx.z;
    A += bz * (long long)NSEQ * 4096;       // att rows, 2048 fp16
    B += bz * 512LL * 4096;                 // vt rows, 2048 fp16

    const int tid = threadIdx.x;
    const int wid = tid >> 5, lane = tid & 31;
    const int wm = wid & 3, wn = wid >> 2;
    const int lr = lane & 15, lc = lane >> 4;
    const int m0 = blockIdx.y * 128, n0 = blockIdx.x * 128;

    const int lrow = tid >> 1;
    const int cb2 = (tid & 1) * 2;

    const uint32_t smb = smem_u32(sm);
    const uint8_t* srcA0 = A + (long long)(m0 + lrow) * 4096 + cb2 * 16;
    const uint8_t* srcB0 = B + (long long)(n0 + lrow) * 4096 + cb2 * 16;

    float acc[2][8][4];
#pragma unroll
    for (int i = 0; i < 2; ++i)
#pragma unroll
        for (int j = 0; j < 8; ++j)
#pragma unroll
            for (int t = 0; t < 4; ++t) acc[i][j][t] = 0.0f;

    const int S = NSEQ / 32;  // 64

#define AV_ISSUE(s)                                                           \
    do {                                                                      \
        const uint32_t stb = smb + ((s) % AV_STAGES) * AV_STAGE;              \
        const uint8_t* pa = srcA0 + (s) * 64;                                 \
        const uint8_t* pb = srcB0 + (s) * 64;                                 \
        _Pragma("unroll")                                                     \
        for (int c = 0; c < 2; ++c)                                           \
            cp16(plainb_addr(stb, lrow, cb2 + c), pa + c * 16);               \
        _Pragma("unroll")                                                     \
        for (int c = 0; c < 2; ++c)                                           \
            cp16(plainb_addr(stb + 8192, lrow, cb2 + c), pb + c * 16);        \
        cp_commit();                                                          \
    } while (0)

    AV_ISSUE(0);
    AV_ISSUE(1);
    AV_ISSUE(2);

    for (int s = 0; s < S; ++s) {
        if (s + 1 < S) cp_wait<2>(); else cp_wait<0>();
        __syncthreads();
        if (s + 3 < S) AV_ISSUE(s + 3);

        const uint32_t bufA = smb + (s % AV_STAGES) * AV_STAGE;
        const uint32_t bufB = bufA + 8192;

#pragma unroll
        for (int kk = 0; kk < 2; ++kk) {
            const int c = kk * 2 + lc;
            uint32_t aF[2][4];
#pragma unroll
            for (int mi = 0; mi < 2; ++mi) {
                const int r = wm * 32 + mi * 16 + lr;
                ldsm4(aF[mi], plainb_addr(bufA, r, c));
            }
#pragma unroll
            for (int g = 0; g < 4; ++g) {
                const int r = wn * 64 + g * 16 + lr;
                uint32_t b[4];
                ldsm4(b, plainb_addr(bufB, r, c));
#pragma unroll
                for (int mi = 0; mi < 2; ++mi) {
                    mma_f16(acc[mi][2 * g],     aF[mi], b[0], b[2]);
                    mma_f16(acc[mi][2 * g + 1], aF[mi], b[1], b[3]);
                }
            }
        }
    }
#undef AV_ISSUE

#pragma unroll
    for (int mi = 0; mi < 2; ++mi) {
        const long long r0 = bz * NSEQ + m0 + wm * 32 + mi * 16 + (lane >> 2);
#pragma unroll
        for (int nj = 0; nj < 8; ++nj) {
            const int col = n0 + wn * 64 + nj * 8 + 2 * (lane & 3);
            const long long cb0 = (long long)(col >> 5) * 128 + (col & 31) * 2;
            uint32_t hi, lo;
            split2h(acc[mi][nj][0], acc[mi][nj][1], hi, lo);
            uint8_t* p = Cs + r0 * 2048 + cb0;
            *(uint32_t*)p = hi;
            *(uint32_t*)(p + 64) = lo;
            split2h(acc[mi][nj][2], acc[mi][nj][3], hi, lo);
            p = Cs + (r0 + 8) * 2048 + cb0;
            *(uint32_t*)p = hi;
            *(uint32_t*)(p + 64) = lo;
        }
    }
}

// ---------------------------------------------------------------------------
// Mt = Wk @ Wq^T (fp32 tiled SIMT), output split fp16 [512 rows x 2048B].
// Mt[b][a] = sum_m Wk[b,m] * Wq[a,m].
// ---------------------------------------------------------------------------
__global__ __launch_bounds__(256)
void wqwk_split(const float* __restrict__ Wk, const float* __restrict__ Wq,
                uint8_t* __restrict__ out)
{
    __shared__ float sk[64][36], sq[64][36];
    const int b0 = blockIdx.y * 64;
    const int a0 = blockIdx.x * 64;
    const int tid = threadIdx.x;
    const int ty = tid >> 4, tx = tid & 15;

    float acc[4][4];
#pragma unroll
    for (int i = 0; i < 4; ++i)
#pragma unroll
        for (int j = 0; j < 4; ++j) acc[i][j] = 0.0f;

    const int lr = tid >> 2;
    const int lcb = (tid & 3) * 8;

    for (int k0 = 0; k0 < 512; k0 += 32) {
        *(float4*)&sk[lr][lcb]     = *(const float4*)(Wk + (long long)(b0 + lr) * 512 + k0 + lcb);
        *(float4*)&sk[lr][lcb + 4] = *(const float4*)(Wk + (long long)(b0 + lr) * 512 + k0 + lcb + 4);
        *(float4*)&sq[lr][lcb]     = *(const float4*)(Wq + (long long)(a0 + lr) * 512 + k0 + lcb);
        *(float4*)&sq[lr][lcb + 4] = *(const float4*)(Wq + (long long)(a0 + lr) * 512 + k0 + lcb + 4);
        __syncthreads();
#pragma unroll 8
        for (int kk = 0; kk < 32; ++kk)
#pragma unroll
            for (int i = 0; i < 4; ++i)
#pragma unroll
                for (int j = 0; j < 4; ++j)
                    acc[i][j] = fmaf(sk[ty * 4 + i][kk], sq[tx * 4 + j][kk], acc[i][j]);
        __syncthreads();
    }

#pragma unroll
    for (int i = 0; i < 4; ++i) {
        const int b = b0 + ty * 4 + i;
#pragma unroll
        for (int jp = 0; jp < 2; ++jp) {
            const int a = a0 + tx * 4 + jp * 2;
            uint32_t hi, lo;
            split2h(acc[i][jp * 2], acc[i][jp * 2 + 1], hi, lo);
            uint8_t* p = out + (long long)b * 2048 + (a >> 5) * 128 + (a & 31) * 2;
            *(uint32_t*)p = hi;
            *(uint32_t*)(p + 64) = lo;
        }
    }
}

// u[m] = sum_h Wk[m,h] * bq[h].  One warp per m.
__global__ __launch_bounds__(256)
void compute_u(const float* __restrict__ Wk, const float* __restrict__ bq,
               float* __restrict__ u)
{
    const int w = (blockIdx.x * 256 + threadIdx.x) >> 5;
    const int lane = threadIdx.x & 31;
    if (w >= 512) return;
    const float* row = Wk + (long long)w * 512;
    float s = 0.0f;
    for (int h = lane; h < 512; h += 32) s += row[h] * bq[h];
#pragma unroll
    for (int off = 16; off > 0; off >>= 1)
        s += __shfl_xor_sync(0xFFFFFFFFu, s, off);
    if (lane == 0) u[w] = s;
}

// c[i] = sum_m h[i,m] * u[m].  One warp per row.
__global__ __launch_bounds__(256)
void compute_c(const float* __restrict__ h, const float* __restrict__ u,
               float* __restrict__ c)
{
    const long long w = ((long long)blockIdx.x * 256 + threadIdx.x) >> 5;
    const int lane = threadIdx.x & 31;
    const float* row = h + w * 512;
    float s = 0.0f;
    for (int m = lane; m < 512; m += 32) s += row[m] * u[m];
#pragma unroll
    for (int off = 16; off > 0; off >>= 1)
        s += __shfl_xor_sync(0xFFFFFFFFu, s, off);
    if (lane == 0) c[w] = s;
}

// ---------------------------------------------------------------------------
// Prep kernels
// ---------------------------------------------------------------------------
__global__ __launch_bounds__(256)
void split16_rows512(const float* __restrict__ in, uint8_t* __restrict__ out)
{
    const long long i8 = ((long long)blockIdx.x * 256 + threadIdx.x) * 8;
    const long long row = i8 >> 9;
    const int col = (int)(i8 & 511);
    const float4 a = *(const float4*)(in + i8);
    const float4 b = *(const float4*)(in + i8 + 4);
    uint4 hi, lo;
    split2h(a.x, a.y, hi.x, lo.x);
    split2h(a.z, a.w, hi.y, lo.y);
    split2h(b.x, b.y, hi.z, lo.z);
    split2h(b.z, b.w, hi.w, lo.w);
    uint8_t* p = out + row * 2048 + (col >> 5) * 128 + (col & 31) * 2;
    *(uint4*)p = hi;
    *(uint4*)(p + 64) = lo;
}

__global__ __launch_bounds__(256)
void transpose_plain_w16(const float* __restrict__ in, __half* __restrict__ out)
{
    __shared__ float t[32][33];
    const int c0 = blockIdx.x * 32;
    const int r0 = blockIdx.y * 32;
    const int x = threadIdx.x;
    const int y = threadIdx.y;
#pragma unroll
    for (int j = 0; j < 32; j += 8)
        t[y + j][x] = in[(long long)(r0 + y + j) * 512 + c0 + x];
    __syncthreads();
#pragma unroll
    for (int j = 0; j < 32; j += 8)
        out[(long long)(c0 + y + j) * 512 + r0 + x] = __float2half_rn(t[x][y + j]);
}

__global__ __launch_bounds__(256)
void vt_transpose16(const __half* __restrict__ v, __half* __restrict__ vt)
{
    __shared__ __half t[32][33];
    const long long b = blockIdx.z;
    const int h0 = blockIdx.x * 32;
    const int n0 = blockIdx.y * 32;
    const int x = threadIdx.x;
    const int y = threadIdx.y;
#pragma unroll
    for (int j = 0; j < 32; j += 8)
        t[y + j][x] = v[(b * 2048 + n0 + y + j) * 512 + h0 + x];
    __syncthreads();
#pragma unroll
    for (int j = 0; j < 32; j += 8)
        vt[b * 512 * 2048 + (long long)(h0 + y + j) * 2048 + n0 + x] = t[x][y + j];
}

// ---------------------------------------------------------------------------
// Row softmax (2048) fp32 -> fp16 with per-column bias c_j, gated exp.
// cvec points at c entries for the FIRST batch of this launch.
// ---------------------------------------------------------------------------
__global__ __launch_bounds__(256)
void softmax_f16_kernel(const float* __restrict__ att, __half* __restrict__ outh,
                        const float* __restrict__ cvec)
{
    const float* row = att + (long long)blockIdx.x * NSEQ;
    __half* orow = outh + (long long)blockIdx.x * NSEQ;
    const float* cb = cvec + (((long long)blockIdx.x >> 11) << 11);
    __shared__ float sred[8];
    const int tid = threadIdx.x;
    const int wid = tid >> 5;
    const int lane = tid & 31;
    const int c0 = tid * 8;

    float r[8];
    *(float4*)&r[0] = *(const float4*)(row + c0);
    *(float4*)&r[4] = *(const float4*)(row + c0 + 4);
    float cv[8];
    *(float4*)&cv[0] = *(const float4*)(cb + c0);
    *(float4*)&cv[4] = *(const float4*)(cb + c0 + 4);
#pragma unroll
    for (int p = 0; p < 8; ++p) r[p] += cv[p];

    float lmax = r[0];
#pragma unroll
    for (int p = 1; p < 8; ++p) lmax = fmaxf(lmax, r[p]);
    float m = lmax;
#pragma unroll
    for (int off = 16; off > 0; off >>= 1)
        m = fmaxf(m, __shfl_xor_sync(0xFFFFFFFFu, m, off));
    if (lane == 0) sred[wid] = m;
    __syncthreads();
    float M = sred[0];
#pragma unroll
    for (int w = 1; w < 8; ++w) M = fmaxf(M, sred[w]);

    float sum = 0.0f;
    if (lmax - M > -25.0f) {
#pragma unroll
        for (int p = 0; p < 8; ++p) {
            r[p] = __expf(r[p] - M);
            sum += r[p];
        }
    } else {
#pragma unroll
        for (int p = 0; p < 8; ++p) r[p] = 0.0f;
    }

#pragma unroll
    for (int off = 16; off > 0; off >>= 1)
        sum += __shfl_xor_sync(0xFFFFFFFFu, sum, off);
    __syncthreads();
    if (lane == 0) sred[wid] = sum;
    __syncthreads();
    float S = sred[0];
#pragma unroll
    for (int w = 1; w < 8; ++w) S += sred[w];
    const float inv = 1.0f / S;

    __half2 hh[4];
#pragma unroll
    for (int p = 0; p < 4; ++p)
        hh[p] = __floats2half2_rn(r[2 * p] * inv, r[2 * p + 1] * inv);
    *(uint4*)(orow + c0) = *(uint4*)hh;
}

// ---------------------------------------------------------------------------
// Launch. Algebra: softmax(q k^T) = softmax(h (WqWk^T) h^T + 1*c^T) with
// c_j = h_j . (Wk bq); row-constant terms drop inside softmax. So the k
// projection is eliminated: t = h@M (half the projection work), logits = t@h^T
// reusing hs as the B operand. Stream fork/join as in round 11.
// ---------------------------------------------------------------------------
extern "C" void kernel_launch(void* const* d_in, const int* in_sizes, int n_in,
                              void* d_out, int out_size)
{
    (void)in_sizes; (void)n_in; (void)out_size;
    const float* h  = (const float*)d_in[1];
    const float* Wv = (const float*)d_in[2];
    const float* bv = (const float*)d_in[3];
    const float* Wk = (const float*)d_in[4];
    const float* bk = (const float*)d_in[5];
    const float* Wq = (const float*)d_in[6];
    const float* bq = (const float*)d_in[7];
    const float* W1 = (const float*)d_in[8];
    const float* b1 = (const float*)d_in[9];
    const float* W2 = (const float*)d_in[10];
    const float* b2 = (const float*)d_in[11];
    (void)bk;   // row-constant in softmax; drops out
    float* out = (float*)d_out;

    uint8_t *hs, *ts, *v16, *vt16, *os, *hids, *wms, *wv16, *w116, *w216;
    float *att, *uvec, *cvec;
    __half* atth;
    cudaGetSymbolAddress((void**)&hs,   g_h_s);
    cudaGetSymbolAddress((void**)&ts,   g_t_s);
    cudaGetSymbolAddress((void**)&v16,  g_v16);
    cudaGetSymbolAddress((void**)&vt16, g_vt16);
    cudaGetSymbolAddress((void**)&os,   g_o_s);
    cudaGetSymbolAddress((void**)&hids, g_hid_s);
    cudaGetSymbolAddress((void**)&wms,  g_wm_s);
    cudaGetSymbolAddress((void**)&wv16, g_wv16);
    cudaGetSymbolAddress((void**)&w116, g_w116);
    cudaGetSymbolAddress((void**)&w216, g_w216);
    cudaGetSymbolAddress((void**)&att,  g_att);
    cudaGetSymbolAddress((void**)&atth, g_atth);
    cudaGetSymbolAddress((void**)&uvec, g_u);
    cudaGetSymbolAddress((void**)&cvec, g_c);

    static cudaStream_t s1 = nullptr;
    static cudaEvent_t evFork = nullptr, evMt = nullptr, evA = nullptr,
                       evC = nullptr, evLog0 = nullptr, evJoin = nullptr;
    if (!s1) {
        cudaStreamCreateWithFlags(&s1, cudaStreamNonBlocking);
        cudaEventCreateWithFlags(&evFork, cudaEventDisableTiming);
        cudaEventCreateWithFlags(&evMt,   cudaEventDisableTiming);
        cudaEventCreateWithFlags(&evA,    cudaEventDisableTiming);
        cudaEventCreateWithFlags(&evC,    cudaEventDisableTiming);
        cudaEventCreateWithFlags(&evLog0, cudaEventDisableTiming);
        cudaEventCreateWithFlags(&evJoin, cudaEventDisableTiming);
    }

    cudaFuncSetAttribute(hmma_gemm3<false, 1>, cudaFuncAttributeMaxDynamicSharedMemorySize, G3_SMEM);
    cudaFuncSetAttribute(hmma_gemm3<false, 0>, cudaFuncAttributeMaxDynamicSharedMemorySize, G3_SMEM);
    cudaFuncSetAttribute(hmma_gemm2<true, false, 2>, cudaFuncAttributeMaxDynamicSharedMemorySize, G2_SMEM);
    cudaFuncSetAttribute(hmma_gemm2<true, true,  1>, cudaFuncAttributeMaxDynamicSharedMemorySize, G2_SMEM);
    cudaFuncSetAttribute(hmma_gemm2<true, false, 0>, cudaFuncAttributeMaxDynamicSharedMemorySize, G2_SMEM);
    cudaFuncSetAttribute(hmma_av1, cudaFuncAttributeMaxDynamicSharedMemorySize, AV_SMEM);

    const dim3 tblk(32, 8), tgrd(16, 16);
    const long long sT   = 2048LL * 2048;    // bytes per batch in t/h split
    const long long sATTf = 2048LL * 2048;   // floats per batch of att
    const int HB = BB / 2;

    // ---- fork s1 immediately ----
    cudaEventRecord(evFork, 0);
    cudaStreamWaitEvent(s1, evFork, 0);

    // s1: Mt = Wk@Wq^T split (needed by t-proj)
    {
        dim3 grd(8, 8);
        wqwk_split<<<grd, 256, 0, s1>>>(Wk, Wq, wms);
    }
    cudaEventRecord(evMt, s1);
    // s1: remaining weight transposes + column-bias c
    transpose_plain_w16<<<tgrd, tblk, 0, s1>>>(Wv, (__half*)wv16);
    transpose_plain_w16<<<tgrd, tblk, 0, s1>>>(W1, (__half*)w116);
    transpose_plain_w16<<<tgrd, tblk, 0, s1>>>(W2, (__half*)w216);
    compute_u<<<64, 256, 0, s1>>>(Wk, bq, uvec);
    compute_c<<<BN_ROWS / 8, 256, 0, s1>>>(h, uvec, cvec);
    cudaEventRecord(evC, s1);

    // ---- main: h split ----
    split16_rows512<<<(BN_ROWS * 512 / 8) / 256, 256>>>(h, hs);
    cudaEventRecord(evA, 0);

    // s1: v-proj (needs hs) + v^T
    cudaStreamWaitEvent(s1, evA, 0);
    {
        dim3 grd(512 / 128, BN_ROWS / 128, 1);
        hmma_gemm2<true, false, 2><<<grd, 256, G2_SMEM, s1>>>(
            hs, wv16, bv, nullptr, v16, 512, 2048, 1024, 1024);
    }
    {
        dim3 blk(32, 8), grd(16, 64, BB);
        vt_transpose16<<<grd, blk, 0, s1>>>((const __half*)v16, (__half*)vt16);
    }

    // ---- main: t-proj (needs hs + Mt) ----
    cudaStreamWaitEvent(0, evMt, 0);
    {
        dim3 grd(512 / 128, BN_ROWS / 128, 1);
        hmma_gemm3<false, 1><<<grd, 256, G3_SMEM>>>(
            hs, wms, nullptr, nullptr, ts, 512, 2048, 2048, 2048, 0, 0, 0);
    }

    // ---- main: logits(H0) = t @ h^T ----
    {
        dim3 grd(NSEQ / 128, NSEQ / 128, HB);
        hmma_gemm3<false, 0><<<grd, 256, G3_SMEM>>>(
            ts, hs, nullptr, att, nullptr,
            512, 2048, 2048, 8192, sT, sT, 2048LL * 8192);
    }
    cudaEventRecord(evLog0, 0);

    // ---- s1: softmax(H0) + AV(H0) ----
    cudaStreamWaitEvent(s1, evLog0, 0);
    softmax_f16_kernel<<<HB * NSEQ, 256, 0, s1>>>(att, atth, cvec);
    {
        dim3 grd(512 / 128, NSEQ / 128, HB);
        hmma_av1<<<grd, 256, AV_SMEM, s1>>>((const uint8_t*)atth, vt16, os);
    }
    cudaEventRecord(evJoin, s1);

    // ---- main: logits(H1), softmax(H1), AV(H1) ----
    {
        dim3 grd(NSEQ / 128, NSEQ / 128, HB);
        hmma_gemm3<false, 0><<<grd, 256, G3_SMEM>>>(
            ts + HB * sT, hs + HB * sT, nullptr,
            att + HB * sATTf, nullptr,
            512, 2048, 2048, 8192, sT, sT, 2048LL * 8192);
    }
    cudaStreamWaitEvent(0, evC, 0);
    softmax_f16_kernel<<<HB * NSEQ, 256>>>(att + HB * sATTf, atth + HB * sATTf,
                                           cvec + (long long)HB * NSEQ);
    cudaStreamWaitEvent(0, evJoin, 0);
    {
        dim3 grd(512 / 128, NSEQ / 128, HB);
        hmma_av1<<<grd, 256, AV_SMEM>>>(
            (const uint8_t*)(atth + HB * sATTf),
            vt16 + (long long)HB * 512 * 4096,
            os + (long long)HB * 2048 * 2048);
    }

    // ---- MLP ----
    {
        dim3 grd(512 / 128, BN_ROWS / 128, 1);
        hmma_gemm2<true, true, 1><<<grd, 256, G2_SMEM>>>(
            os, w116, b1, nullptr, hids, 512, 2048, 1024, 2048);
        hmma_gemm2<true, false, 0><<<grd, 256, G2_SMEM>>>(
            hids, w216, b2, out, nullptr, 512, 2048, 1024, 2048);
    }
}

// round 13
// speedup vs baseline: 1.1977x; 1.0821x over previous
#include <cuda_runtime.h>
#include <cuda_fp16.h>
#include <math.h>
#include <stdint.h>

// Problem dims (fixed)
#define BB 16
#define NSEQ 2048
#define MM 512
#define HH 512
#define BN_ROWS (BB * NSEQ)   // 32768

// ---------------------------------------------------------------------------
// Split layout (fp16): 4 bytes/elem, groups of 32 cols: 128B = 32 hi | 32 lo.
// byte(r, c) = r*rowBytes + (c>>5)*128 + (c&31)*2   (hi; lo at +64)
// Plain fp16 layout: byte(r, c) = r*rowBytes + c*2.
// ---------------------------------------------------------------------------
__device__ __align__(128) uint8_t g_h_s  [(long long)BN_ROWS * HH * 4];     // h split
__device__ __align__(128) uint8_t g_t_s  [(long long)BN_ROWS * HH * 4];     // t = h@M split
__device__ __align__(128) uint8_t g_v16  [(long long)BN_ROWS * HH * 2];     // v plain
__device__ __align__(128) uint8_t g_vt16 [(long long)BN_ROWS * HH * 2];     // v^T plain
__device__ __align__(128) uint8_t g_o16  [(long long)BN_ROWS * HH * 2];     // o plain
__device__ __align__(128) uint8_t g_hid16[(long long)BN_ROWS * HH * 2];     // hid plain
__device__ __align__(128) uint8_t g_wm_s [512LL * 512 * 4];                 // M^T = Wk@Wq^T split
__device__ __align__(128) uint8_t g_wv16 [512LL * 512 * 2];                 // Wv^T plain
__device__ __align__(128) uint8_t g_w116 [512LL * 512 * 2];                 // W1^T plain
__device__ __align__(128) uint8_t g_w216 [512LL * 512 * 2];                 // W2^T plain
__device__ float g_att[(long long)BB * NSEQ * NSEQ];
__device__ __align__(128) __half g_atth[(long long)BB * NSEQ * NSEQ];
__device__ float g_u[512];            // Wk @ bq
__device__ float g_c[BN_ROWS];        // per-column softmax bias c_j = h_j . u

// ---------------------------------------------------------------------------
// Helpers
// ---------------------------------------------------------------------------
__device__ __forceinline__ uint32_t smem_u32(const void* p) {
    uint32_t a;
    asm("{ .reg .u64 t; cvta.to.shared.u64 t, %1; cvt.u32.u64 %0, t; }" : "=r"(a) : "l"(p));
    return a;
}
__device__ __forceinline__ void ldsm4(uint32_t* r, uint32_t addr) {
    asm volatile("ldmatrix.sync.aligned.m8n8.x4.shared.b16 {%0,%1,%2,%3}, [%4];"
                 : "=r"(r[0]), "=r"(r[1]), "=r"(r[2]), "=r"(r[3]) : "r"(addr));
}
__device__ __forceinline__ void mma_f16(float* c, const uint32_t* a,
                                        uint32_t b0, uint32_t b1) {
    asm volatile(
        "mma.sync.aligned.m16n8k16.row.col.f32.f16.f16.f32 "
        "{%0,%1,%2,%3}, {%4,%5,%6,%7}, {%8,%9}, {%0,%1,%2,%3};"
        : "+f"(c[0]), "+f"(c[1]), "+f"(c[2]), "+f"(c[3])
        : "r"(a[0]), "r"(a[1]), "r"(a[2]), "r"(a[3]), "r"(b0), "r"(b1));
}
__device__ __forceinline__ void cp16(uint32_t dst, const void* src) {
    asm volatile("cp.async.cg.shared.global [%0], [%1], 16;" :: "r"(dst), "l"(src));
}
__device__ __forceinline__ void cp_commit() {
    asm volatile("cp.async.commit_group;");
}
template <int N> __device__ __forceinline__ void cp_wait() {
    asm volatile("cp.async.wait_group %0;" :: "n"(N));
}
__device__ __forceinline__ void split2h(float x, float y, uint32_t& hi, uint32_t& lo) {
    __half2 h = __floats2half2_rn(x, y);
    __half2 l = __floats2half2_rn(x - __half2float(h.x), y - __half2float(h.y));
    hi = *(uint32_t*)&h;
    lo = *(uint32_t*)&l;
}

// Plain-fp16 smem tile addressing (64B data per row, 2 rows per 128B line,
// 8-chunk XOR swizzle): conflict-free for ldmatrix and cp.async.
__device__ __forceinline__ uint32_t plainb_addr(uint32_t base, int r, int c) {
    return base + ((r >> 1) << 7) + (((((r & 1) << 2) + c) ^ ((r >> 1) & 7)) << 4);
}

// OUTMODE: 0 = fp32, 1 = split fp16, 2 = plain fp16

// ---------------------------------------------------------------------------
// gemm3: A split, B split, 3 MMAs, chain-batched. CTA 128x128, warp 32x64.
// ---------------------------------------------------------------------------
#define G3_STAGES 3
#define G3_STAGE 32768
#define G3_SMEM (G3_STAGES * G3_STAGE)

template <bool HAS_BIAS, int OUTMODE>
__global__ __launch_bounds__(256, 2)
void hmma_gemm3(const uint8_t* __restrict__ A, const uint8_t* __restrict__ B,
                const float* __restrict__ bias, float* __restrict__ Cf,
                uint8_t* __restrict__ Cs,
                int K, long long ldaB, long long ldbB, long long ldcB,
                long long sA, long long sB, long long sC)
{
    extern __shared__ uint8_t sm[];
    const long long bz = blockIdx.z;
    A += bz * sA;
    B += bz * sB;

    const int tid = threadIdx.x;
    const int wid = tid >> 5, lane = tid & 31;
    const int wm = wid & 3, wn = wid >> 2;
    const int lr = lane & 15, lc = lane >> 4;
    const int m0 = blockIdx.y * 128, n0 = blockIdx.x * 128;

    const int lrow = tid >> 1;
    const int cb = (tid & 1) * 4;
    const int rsw = lrow & 7;

    const uint32_t smb = smem_u32(sm);
    const uint8_t* srcA0 = A + (long long)(m0 + lrow) * ldaB + cb * 16;
    const uint8_t* srcB0 = B + (long long)(n0 + lrow) * ldbB + cb * 16;

    float acc[2][8][4];
#pragma unroll
    for (int i = 0; i < 2; ++i)
#pragma unroll
        for (int j = 0; j < 8; ++j)
#pragma unroll
            for (int t = 0; t < 4; ++t) acc[i][j][t] = 0.0f;

    const int S = K / 32;

#define G3_ISSUE(s)                                                           \
    do {                                                                      \
        const uint32_t dra = smb + ((s) % G3_STAGES) * G3_STAGE + lrow * 128; \
        const uint8_t* pa = srcA0 + (s) * 128;                                \
        const uint8_t* pb = srcB0 + (s) * 128;                                \
        _Pragma("unroll")                                                     \
        for (int c = 0; c < 4; ++c)                                           \
            cp16(dra + (((cb + c) ^ rsw) << 4), pa + c * 16);                 \
        _Pragma("unroll")                                                     \
        for (int c = 0; c < 4; ++c)                                           \
            cp16(dra + 16384 + (((cb + c) ^ rsw) << 4), pb + c * 16);         \
        cp_commit();                                                          \
    } while (0)

    G3_ISSUE(0);
    G3_ISSUE(1);

    for (int s = 0; s < S; ++s) {
        if (s + 1 < S) cp_wait<1>(); else cp_wait<0>();
        __syncthreads();
        if (s + 2 < S) G3_ISSUE(s + 2);

        const uint32_t bufA = smb + (s % G3_STAGES) * G3_STAGE;
        const uint32_t bufB = bufA + 16384;

#pragma unroll
        for (int kk = 0; kk < 2; ++kk) {
            uint32_t aH[2][4], aL[2][4];
            const int byteh = kk * 32 + lc * 16;
#pragma unroll
            for (int mi = 0; mi < 2; ++mi) {
                const int r = wm * 32 + mi * 16 + lr;
                const uint32_t rb = bufA + r * 128;
                const int rs = r & 7;
                ldsm4(aH[mi], rb + ((((byteh) >> 4) ^ rs) << 4));
                ldsm4(aL[mi], rb + ((((byteh + 64) >> 4) ^ rs) << 4));
            }
#pragma unroll
            for (int g = 0; g < 4; ++g) {
                const int r = wn * 64 + g * 16 + lr;
                const uint32_t rb = bufB + r * 128;
                const int rs = r & 7;
                uint32_t bh[4], bl[4];
                ldsm4(bh, rb + ((((byteh) >> 4) ^ rs) << 4));
                ldsm4(bl, rb + ((((byteh + 64) >> 4) ^ rs) << 4));
#pragma unroll
                for (int mi = 0; mi < 2; ++mi) {          // HH
                    mma_f16(acc[mi][2 * g],     aH[mi], bh[0], bh[2]);
                    mma_f16(acc[mi][2 * g + 1], aH[mi], bh[1], bh[3]);
                }
#pragma unroll
                for (int mi = 0; mi < 2; ++mi) {          // HL
                    mma_f16(acc[mi][2 * g],     aH[mi], bl[0], bl[2]);
                    mma_f16(acc[mi][2 * g + 1], aH[mi], bl[1], bl[3]);
                }
#pragma unroll
                for (int mi = 0; mi < 2; ++mi) {          // LH
                    mma_f16(acc[mi][2 * g],     aL[mi], bh[0], bh[2]);
                    mma_f16(acc[mi][2 * g + 1], aL[mi], bh[1], bh[3]);
                }
            }
        }
    }
#undef G3_ISSUE

#pragma unroll
    for (int mi = 0; mi < 2; ++mi) {
        const long long r0 = m0 + wm * 32 + mi * 16 + (lane >> 2);
#pragma unroll
        for (int nj = 0; nj < 8; ++nj) {
            const int col = n0 + wn * 64 + nj * 8 + 2 * (lane & 3);
            float bx = 0.0f, by = 0.0f;
            if (HAS_BIAS) {
                const float2 bvv = *(const float2*)(bias + col);
                bx = bvv.x; by = bvv.y;
            }
            const float x0 = acc[mi][nj][0] + bx;
            const float x1 = acc[mi][nj][1] + by;
            const float x2 = acc[mi][nj][2] + bx;
            const float x3 = acc[mi][nj][3] + by;
            if (OUTMODE == 0) {
                uint8_t* base = (uint8_t*)Cf + bz * sC;
                *(float2*)(base + r0 * ldcB + col * 4)       = make_float2(x0, x1);
                *(float2*)(base + (r0 + 8) * ldcB + col * 4) = make_float2(x2, x3);
            } else {
                uint8_t* base = Cs + bz * sC;
                const long long cb0 = (long long)(col >> 5) * 128 + (col & 31) * 2;
                uint32_t hi, lo;
                split2h(x0, x1, hi, lo);
                uint8_t* p = base + r0 * ldcB + cb0;
                *(uint32_t*)p = hi;
                *(uint32_t*)(p + 64) = lo;
                split2h(x2, x3, hi, lo);
                p = base + (r0 + 8) * ldcB + cb0;
                *(uint32_t*)p = hi;
                *(uint32_t*)(p + 64) = lo;
            }
        }
    }
}

// ---------------------------------------------------------------------------
// gemm2: A split fp16, B plain fp16, 2 MMAs. (v-proj only.)
// ---------------------------------------------------------------------------
#define G2_STAGES 4
#define G2_STAGE 24576
#define G2_SMEM (G2_STAGES * G2_STAGE)

template <bool HAS_BIAS, bool RELU, int OUTMODE>
__global__ __launch_bounds__(256, 2)
void hmma_gemm2(const uint8_t* __restrict__ A, const uint8_t* __restrict__ B,
                const float* __restrict__ bias, float* __restrict__ Cf,
                uint8_t* __restrict__ Cs,
                int K, long long ldaB, long long ldbB, long long ldcB)
{
    extern __shared__ uint8_t sm[];
    const int tid = threadIdx.x;
    const int wid = tid >> 5, lane = tid & 31;
    const int wm = wid & 3, wn = wid >> 2;
    const int lr = lane & 15, lc = lane >> 4;
    const int m0 = blockIdx.y * 128, n0 = blockIdx.x * 128;

    const int lrow = tid >> 1;
    const int cbA = (tid & 1) * 4;
    const int cbB = (tid & 1) * 2;
    const int rsw = lrow & 7;

    const uint32_t smb = smem_u32(sm);
    const uint8_t* srcA0 = A + (long long)(m0 + lrow) * ldaB + cbA * 16;
    const uint8_t* srcB0 = B + (long long)(n0 + lrow) * ldbB + cbB * 16;

    float acc[2][8][4];
#pragma unroll
    for (int i = 0; i < 2; ++i)
#pragma unroll
        for (int j = 0; j < 8; ++j)
#pragma unroll
            for (int t = 0; t < 4; ++t) acc[i][j][t] = 0.0f;

    const int S = K / 32;

#define G2_ISSUE(s)                                                           \
    do {                                                                      \
        const uint32_t stb = smb + ((s) % G2_STAGES) * G2_STAGE;              \
        const uint8_t* pa = srcA0 + (s) * 128;                                \
        const uint8_t* pb = srcB0 + (s) * 64;                                 \
        const uint32_t dra = stb + lrow * 128;                                \
        _Pragma("unroll")                                                     \
        for (int c = 0; c < 4; ++c)                                           \
            cp16(dra + (((cbA + c) ^ rsw) << 4), pa + c * 16);                \
        _Pragma("unroll")                                                     \
        for (int c = 0; c < 2; ++c)                                           \
            cp16(plainb_addr(stb + 16384, lrow, cbB + c), pb + c * 16);       \
        cp_commit();                                                          \
    } while (0)

    G2_ISSUE(0);
    G2_ISSUE(1);
    G2_ISSUE(2);

    for (int s = 0; s < S; ++s) {
        if (s + 1 < S) cp_wait<2>(); else cp_wait<0>();
        __syncthreads();
        if (s + 3 < S) G2_ISSUE(s + 3);

        const uint32_t bufA = smb + (s % G2_STAGES) * G2_STAGE;
        const uint32_t bufB = bufA + 16384;

#pragma unroll
        for (int kk = 0; kk < 2; ++kk) {
            uint32_t aH[2][4], aL[2][4];
            const int byteh = kk * 32 + lc * 16;
#pragma unroll
            for (int mi = 0; mi < 2; ++mi) {
                const int r = wm * 32 + mi * 16 + lr;
                const uint32_t rb = bufA + r * 128;
                const int rs = r & 7;
                ldsm4(aH[mi], rb + ((((byteh) >> 4) ^ rs) << 4));
                ldsm4(aL[mi], rb + ((((byteh + 64) >> 4) ^ rs) << 4));
            }
#pragma unroll
            for (int g = 0; g < 4; ++g) {
                const int r = wn * 64 + g * 16 + lr;
                const int c = kk * 2 + lc;
                uint32_t b[4];
                ldsm4(b, plainb_addr(bufB, r, c));
#pragma unroll
                for (int mi = 0; mi < 2; ++mi) {          // H*b
                    mma_f16(acc[mi][2 * g],     aH[mi], b[0], b[2]);
                    mma_f16(acc[mi][2 * g + 1], aH[mi], b[1], b[3]);
                }
#pragma unroll
                for (int mi = 0; mi < 2; ++mi) {          // L*b
                    mma_f16(acc[mi][2 * g],     aL[mi], b[0], b[2]);
                    mma_f16(acc[mi][2 * g + 1], aL[mi], b[1], b[3]);
                }
            }
        }
    }
#undef G2_ISSUE

#pragma unroll
    for (int mi = 0; mi < 2; ++mi) {
        const long long r0 = m0 + wm * 32 + mi * 16 + (lane >> 2);
#pragma unroll
        for (int nj = 0; nj < 8; ++nj) {
            const int col = n0 + wn * 64 + nj * 8 + 2 * (lane & 3);
            float bx = 0.0f, by = 0.0f;
            if (HAS_BIAS) {
                const float2 bvv = *(const float2*)(bias + col);
                bx = bvv.x; by = bvv.y;
            }
            float x0 = acc[mi][nj][0] + bx;
            float x1 = acc[mi][nj][1] + by;
            float x2 = acc[mi][nj][2] + bx;
            float x3 = acc[mi][nj][3] + by;
            if (RELU) {
                x0 = fmaxf(x0, 0.0f); x1 = fmaxf(x1, 0.0f);
                x2 = fmaxf(x2, 0.0f); x3 = fmaxf(x3, 0.0f);
            }
            if (OUTMODE == 0) {
                *(float2*)((uint8_t*)Cf + r0 * ldcB + col * 4)       = make_float2(x0, x1);
                *(float2*)((uint8_t*)Cf + (r0 + 8) * ldcB + col * 4) = make_float2(x2, x3);
            } else if (OUTMODE == 1) {
                const long long cb0 = (long long)(col >> 5) * 128 + (col & 31) * 2;
                uint32_t hi, lo;
                split2h(x0, x1, hi, lo);
                uint8_t* p = Cs + r0 * ldcB + cb0;
                *(uint32_t*)p = hi;
                *(uint32_t*)(p + 64) = lo;
                split2h(x2, x3, hi, lo);
                p = Cs + (r0 + 8) * ldcB + cb0;
                *(uint32_t*)p = hi;
                *(uint32_t*)(p + 64) = lo;
            } else {
                __half2 v01 = __floats2half2_rn(x0, x1);
                __half2 v23 = __floats2half2_rn(x2, x3);
                *(uint32_t*)(Cs + r0 * ldcB + col * 2)       = *(uint32_t*)&v01;
                *(uint32_t*)(Cs + (r0 + 8) * ldcB + col * 2) = *(uint32_t*)&v23;
            }
        }
    }
}

// ---------------------------------------------------------------------------
// gemm1: A plain fp16, B plain fp16, 1 MMA (+bias, relu). For the MLP.
// OUTMODE 0 = fp32 out, 2 = plain fp16 out.
// ---------------------------------------------------------------------------
#define G1_STAGES 4
#define G1_STAGE 16384
#define G1_SMEM (G1_STAGES * G1_STAGE)

template <bool RELU, int OUTMODE>
__global__ __launch_bounds__(256, 2)
void hmma_gemm1(const uint8_t* __restrict__ A, const uint8_t* __restrict__ B,
                const float* __restrict__ bias, float* __restrict__ Cf,
                uint8_t* __restrict__ Cs,
                int K, long long ldaB, long long ldbB, long long ldcB)
{
    extern __shared__ uint8_t sm[];
    const int tid = threadIdx.x;
    const int wid = tid >> 5, lane = tid & 31;
    const int wm = wid & 3, wn = wid >> 2;
    const int lr = lane & 15, lc = lane >> 4;
    const int m0 = blockIdx.y * 128, n0 = blockIdx.x * 128;

    const int lrow = tid >> 1;
    const int cb2 = (tid & 1) * 2;

    const uint32_t smb = smem_u32(sm);
    const uint8_t* srcA0 = A + (long long)(m0 + lrow) * ldaB + cb2 * 16;
    const uint8_t* srcB0 = B + (long long)(n0 + lrow) * ldbB + cb2 * 16;

    float acc[2][8][4];
#pragma unroll
    for (int i = 0; i < 2; ++i)
#pragma unroll
        for (int j = 0; j < 8; ++j)
#pragma unroll
            for (int t = 0; t < 4; ++t) acc[i][j][t] = 0.0f;

    const int S = K / 32;

#define G1_ISSUE(s)                                                           \
    do {                                                                      \
        const uint32_t stb = smb + ((s) % G1_STAGES) * G1_STAGE;              \
        const uint8_t* pa = srcA0 + (s) * 64;                                 \
        const uint8_t* pb = srcB0 + (s) * 64;                                 \
        _Pragma("unroll")                                                     \
        for (int c = 0; c < 2; ++c)                                           \
            cp16(plainb_addr(stb, lrow, cb2 + c), pa + c * 16);               \
        _Pragma("unroll")                                                     \
        for (int c = 0; c < 2; ++c)                                           \
            cp16(plainb_addr(stb + 8192, lrow, cb2 + c), pb + c * 16);        \
        cp_commit();                                                          \
    } while (0)

    G1_ISSUE(0);
    G1_ISSUE(1);
    G1_ISSUE(2);

    for (int s = 0; s < S; ++s) {
        if (s + 1 < S) cp_wait<2>(); else cp_wait<0>();
        __syncthreads();
        if (s + 3 < S) G1_ISSUE(s + 3);

        const uint32_t bufA = smb + (s % G1_STAGES) * G1_STAGE;
        const uint32_t bufB = bufA + 8192;

#pragma unroll
        for (int kk = 0; kk < 2; ++kk) {
            const int c = kk * 2 + lc;
            uint32_t aF[2][4];
#pragma unroll
            for (int mi = 0; mi < 2; ++mi) {
                const int r = wm * 32 + mi * 16 + lr;
                ldsm4(aF[mi], plainb_addr(bufA, r, c));
            }
#pragma unroll
            for (int g = 0; g < 4; ++g) {
                const int r = wn * 64 + g * 16 + lr;
                uint32_t b[4];
                ldsm4(b, plainb_addr(bufB, r, c));
#pragma unroll
                for (int mi = 0; mi < 2; ++mi) {
                    mma_f16(acc[mi][2 * g],     aF[mi], b[0], b[2]);
                    mma_f16(acc[mi][2 * g + 1], aF[mi], b[1], b[3]);
                }
            }
        }
    }
#undef G1_ISSUE

#pragma unroll
    for (int mi = 0; mi < 2; ++mi) {
        const long long r0 = m0 + wm * 32 + mi * 16 + (lane >> 2);
#pragma unroll
        for (int nj = 0; nj < 8; ++nj) {
            const int col = n0 + wn * 64 + nj * 8 + 2 * (lane & 3);
            const float2 bvv = *(const float2*)(bias + col);
            float x0 = acc[mi][nj][0] + bvv.x;
            float x1 = acc[mi][nj][1] + bvv.y;
            float x2 = acc[mi][nj][2] + bvv.x;
            float x3 = acc[mi][nj][3] + bvv.y;
            if (RELU) {
                x0 = fmaxf(x0, 0.0f); x1 = fmaxf(x1, 0.0f);
                x2 = fmaxf(x2, 0.0f); x3 = fmaxf(x3, 0.0f);
            }
            if (OUTMODE == 0) {
                *(float2*)((uint8_t*)Cf + r0 * ldcB + col * 4)       = make_float2(x0, x1);
                *(float2*)((uint8_t*)Cf + (r0 + 8) * ldcB + col * 4) = make_float2(x2, x3);
            } else {
                __half2 v01 = __floats2half2_rn(x0, x1);
                __half2 v23 = __floats2half2_rn(x2, x3);
                *(uint32_t*)(Cs + r0 * ldcB + col * 2)       = *(uint32_t*)&v01;
                *(uint32_t*)(Cs + (r0 + 8) * ldcB + col * 2) = *(uint32_t*)&v23;
            }
        }
    }
}

// ---------------------------------------------------------------------------
// av1: o[b] = att[b] @ vt[b]^T; both plain fp16, 1 MMA. Out: o PLAIN fp16.
// ---------------------------------------------------------------------------
#define AV_STAGES 4
#define AV_STAGE 16384
#define AV_SMEM (AV_STAGES * AV_STAGE)

__global__ __launch_bounds__(256, 2)
void hmma_av1(const uint8_t* __restrict__ A, const uint8_t* __restrict__ B,
              uint8_t* __restrict__ Cs)
{
    extern __shared__ uint8_t sm[];
    const long long bz = blockIdx.z;
    A += bz * (long long)NSEQ * 4096;       // att rows, 2048 fp16
    B += bz * 512LL * 4096;                 // vt rows, 2048 fp16

    const int tid = threadIdx.x;
    const int wid = tid >> 5, lane = tid & 31;
    const int wm = wid & 3, wn = wid >> 2;
    const int lr = lane & 15, lc = lane >> 4;
    const int m0 = blockIdx.y * 128, n0 = blockIdx.x * 128;

    const int lrow = tid >> 1;
    const int cb2 = (tid & 1) * 2;

    const uint32_t smb = smem_u32(sm);
    const uint8_t* srcA0 = A + (long long)(m0 + lrow) * 4096 + cb2 * 16;
    const uint8_t* srcB0 = B + (long long)(n0 + lrow) * 4096 + cb2 * 16;

    float acc[2][8][4];
#pragma unroll
    for (int i = 0; i < 2; ++i)
#pragma unroll
        for (int j = 0; j < 8; ++j)
#pragma unroll
            for (int t = 0; t < 4; ++t) acc[i][j][t] = 0.0f;

    const int S = NSEQ / 32;  // 64

#define AV_ISSUE(s)                                                           \
    do {                                                                      \
        const uint32_t stb = smb + ((s) % AV_STAGES) * AV_STAGE;              \
        const uint8_t* pa = srcA0 + (s) * 64;                                 \
        const uint8_t* pb = srcB0 + (s) * 64;                                 \
        _Pragma("unroll")                                                     \
        for (int c = 0; c < 2; ++c)                                           \
            cp16(plainb_addr(stb, lrow, cb2 + c), pa + c * 16);               \
        _Pragma("unroll")                                                     \
        for (int c = 0; c < 2; ++c)                                           \
            cp16(plainb_addr(stb + 8192, lrow, cb2 + c), pb + c * 16);        \
        cp_commit();                                                          \
    } while (0)

    AV_ISSUE(0);
    AV_ISSUE(1);
    AV_ISSUE(2);

    for (int s = 0; s < S; ++s) {
        if (s + 1 < S) cp_wait<2>(); else cp_wait<0>();
        __syncthreads();
        if (s + 3 < S) AV_ISSUE(s + 3);

        const uint32_t bufA = smb + (s % AV_STAGES) * AV_STAGE;
        const uint32_t bufB = bufA + 8192;

#pragma unroll
        for (int kk = 0; kk < 2; ++kk) {
            const int c = kk * 2 + lc;
            uint32_t aF[2][4];
#pragma unroll
            for (int mi = 0; mi < 2; ++mi) {
                const int r = wm * 32 + mi * 16 + lr;
                ldsm4(aF[mi], plainb_addr(bufA, r, c));
            }
#pragma unroll
            for (int g = 0; g < 4; ++g) {
                const int r = wn * 64 + g * 16 + lr;
                uint32_t b[4];
                ldsm4(b, plainb_addr(bufB, r, c));
#pragma unroll
                for (int mi = 0; mi < 2; ++mi) {
                    mma_f16(acc[mi][2 * g],     aF[mi], b[0], b[2]);
                    mma_f16(acc[mi][2 * g + 1], aF[mi], b[1], b[3]);
                }
            }
        }
    }
#undef AV_ISSUE

    // epilogue: o plain fp16 (row bytes 1024)
#pragma unroll
    for (int mi = 0; mi < 2; ++mi) {
        const long long r0 = bz * NSEQ + m0 + wm * 32 + mi * 16 + (lane >> 2);
#pragma unroll
        for (int nj = 0; nj < 8; ++nj) {
            const int col = n0 + wn * 64 + nj * 8 + 2 * (lane & 3);
            __half2 v01 = __floats2half2_rn(acc[mi][nj][0], acc[mi][nj][1]);
            __half2 v23 = __floats2half2_rn(acc[mi][nj][2], acc[mi][nj][3]);
            *(uint32_t*)(Cs + r0 * 1024 + col * 2)       = *(uint32_t*)&v01;
            *(uint32_t*)(Cs + (r0 + 8) * 1024 + col * 2) = *(uint32_t*)&v23;
        }
    }
}

// ---------------------------------------------------------------------------
// Mt = Wk @ Wq^T (fp32 tiled SIMT), output split fp16 [512 rows x 2048B].
// ---------------------------------------------------------------------------
__global__ __launch_bounds__(256)
void wqwk_split(const float* __restrict__ Wk, const float* __restrict__ Wq,
                uint8_t* __restrict__ out)
{
    __shared__ float sk[64][36], sq[64][36];
    const int b0 = blockIdx.y * 64;
    const int a0 = blockIdx.x * 64;
    const int tid = threadIdx.x;
    const int ty = tid >> 4, tx = tid & 15;

    float acc[4][4];
#pragma unroll
    for (int i = 0; i < 4; ++i)
#pragma unroll
        for (int j = 0; j < 4; ++j) acc[i][j] = 0.0f;

    const int lr = tid >> 2;
    const int lcb = (tid & 3) * 8;

    for (int k0 = 0; k0 < 512; k0 += 32) {
        *(float4*)&sk[lr][lcb]     = *(const float4*)(Wk + (long long)(b0 + lr) * 512 + k0 + lcb);
        *(float4*)&sk[lr][lcb + 4] = *(const float4*)(Wk + (long long)(b0 + lr) * 512 + k0 + lcb + 4);
        *(float4*)&sq[lr][lcb]     = *(const float4*)(Wq + (long long)(a0 + lr) * 512 + k0 + lcb);
        *(float4*)&sq[lr][lcb + 4] = *(const float4*)(Wq + (long long)(a0 + lr) * 512 + k0 + lcb + 4);
        __syncthreads();
#pragma unroll 8
        for (int kk = 0; kk < 32; ++kk)
#pragma unroll
            for (int i = 0; i < 4; ++i)
#pragma unroll
                for (int j = 0; j < 4; ++j)
                    acc[i][j] = fmaf(sk[ty * 4 + i][kk], sq[tx * 4 + j][kk], acc[i][j]);
        __syncthreads();
    }

#pragma unroll
    for (int i = 0; i < 4; ++i) {
        const int b = b0 + ty * 4 + i;
#pragma unroll
        for (int jp = 0; jp < 2; ++jp) {
            const int a = a0 + tx * 4 + jp * 2;
            uint32_t hi, lo;
            split2h(acc[i][jp * 2], acc[i][jp * 2 + 1], hi, lo);
            uint8_t* p = out + (long long)b * 2048 + (a >> 5) * 128 + (a & 31) * 2;
            *(uint32_t*)p = hi;
            *(uint32_t*)(p + 64) = lo;
        }
    }
}

// u[m] = sum_h Wk[m,h] * bq[h].  One warp per m.
__global__ __launch_bounds__(256)
void compute_u(const float* __restrict__ Wk, const float* __restrict__ bq,
               float* __restrict__ u)
{
    const int w = (blockIdx.x * 256 + threadIdx.x) >> 5;
    const int lane = threadIdx.x & 31;
    if (w >= 512) return;
    const float* row = Wk + (long long)w * 512;
    float s = 0.0f;
    for (int h = lane; h < 512; h += 32) s += row[h] * bq[h];
#pragma unroll
    for (int off = 16; off > 0; off >>= 1)
        s += __shfl_xor_sync(0xFFFFFFFFu, s, off);
    if (lane == 0) u[w] = s;
}

// c[i] = sum_m h[i,m] * u[m].  One warp per row.
__global__ __launch_bounds__(256)
void compute_c(const float* __restrict__ h, const float* __restrict__ u,
               float* __restrict__ c)
{
    const long long w = ((long long)blockIdx.x * 256 + threadIdx.x) >> 5;
    const int lane = threadIdx.x & 31;
    const float* row = h + w * 512;
    float s = 0.0f;
    for (int m = lane; m < 512; m += 32) s += row[m] * u[m];
#pragma unroll
    for (int off = 16; off > 0; off >>= 1)
        s += __shfl_xor_sync(0xFFFFFFFFu, s, off);
    if (lane == 0) c[w] = s;
}

// ---------------------------------------------------------------------------
// Prep kernels
// ---------------------------------------------------------------------------
__global__ __launch_bounds__(256)
void split16_rows512(const float* __restrict__ in, uint8_t* __restrict__ out)
{
    const long long i8 = ((long long)blockIdx.x * 256 + threadIdx.x) * 8;
    const long long row = i8 >> 9;
    const int col = (int)(i8 & 511);
    const float4 a = *(const float4*)(in + i8);
    const float4 b = *(const float4*)(in + i8 + 4);
    uint4 hi, lo;
    split2h(a.x, a.y, hi.x, lo.x);
    split2h(a.z, a.w, hi.y, lo.y);
    split2h(b.x, b.y, hi.z, lo.z);
    split2h(b.z, b.w, hi.w, lo.w);
    uint8_t* p = out + row * 2048 + (col >> 5) * 128 + (col & 31) * 2;
    *(uint4*)p = hi;
    *(uint4*)(p + 64) = lo;
}

__global__ __launch_bounds__(256)
void transpose_plain_w16(const float* __restrict__ in, __half* __restrict__ out)
{
    __shared__ float t[32][33];
    const int c0 = blockIdx.x * 32;
    const int r0 = blockIdx.y * 32;
    const int x = threadIdx.x;
    const int y = threadIdx.y;
#pragma unroll
    for (int j = 0; j < 32; j += 8)
        t[y + j][x] = in[(long long)(r0 + y + j) * 512 + c0 + x];
    __syncthreads();
#pragma unroll
    for (int j = 0; j < 32; j += 8)
        out[(long long)(c0 + y + j) * 512 + r0 + x] = __float2half_rn(t[x][y + j]);
}

__global__ __launch_bounds__(256)
void vt_transpose16(const __half* __restrict__ v, __half* __restrict__ vt)
{
    __shared__ __half t[32][33];
    const long long b = blockIdx.z;
    const int h0 = blockIdx.x * 32;
    const int n0 = blockIdx.y * 32;
    const int x = threadIdx.x;
    const int y = threadIdx.y;
#pragma unroll
    for (int j = 0; j < 32; j += 8)
        t[y + j][x] = v[(b * 2048 + n0 + y + j) * 512 + h0 + x];
    __syncthreads();
#pragma unroll
    for (int j = 0; j < 32; j += 8)
        vt[b * 512 * 2048 + (long long)(h0 + y + j) * 2048 + n0 + x] = t[x][y + j];
}

// ---------------------------------------------------------------------------
// Row softmax (2048) fp32 -> fp16 with per-column bias c_j, gated exp.
// ---------------------------------------------------------------------------
__global__ __launch_bounds__(256)
void softmax_f16_kernel(const float* __restrict__ att, __half* __restrict__ outh,
                        const float* __restrict__ cvec)
{
    const float* row = att + (long long)blockIdx.x * NSEQ;
    __half* orow = outh + (long long)blockIdx.x * NSEQ;
    const float* cb = cvec + (((long long)blockIdx.x >> 11) << 11);
    __shared__ float sred[8];
    const int tid = threadIdx.x;
    const int wid = tid >> 5;
    const int lane = tid & 31;
    const int c0 = tid * 8;

    float r[8];
    *(float4*)&r[0] = *(const float4*)(row + c0);
    *(float4*)&r[4] = *(const float4*)(row + c0 + 4);
    float cv[8];
    *(float4*)&cv[0] = *(const float4*)(cb + c0);
    *(float4*)&cv[4] = *(const float4*)(cb + c0 + 4);
#pragma unroll
    for (int p = 0; p < 8; ++p) r[p] += cv[p];

    float lmax = r[0];
#pragma unroll
    for (int p = 1; p < 8; ++p) lmax = fmaxf(lmax, r[p]);
    float m = lmax;
#pragma unroll
    for (int off = 16; off > 0; off >>= 1)
        m = fmaxf(m, __shfl_xor_sync(0xFFFFFFFFu, m, off));
    if (lane == 0) sred[wid] = m;
    __syncthreads();
    float M = sred[0];
#pragma unroll
    for (int w = 1; w < 8; ++w) M = fmaxf(M, sred[w]);

    float sum = 0.0f;
    if (lmax - M > -25.0f) {
#pragma unroll
        for (int p = 0; p < 8; ++p) {
            r[p] = __expf(r[p] - M);
            sum += r[p];
        }
    } else {
#pragma unroll
        for (int p = 0; p < 8; ++p) r[p] = 0.0f;
    }

#pragma unroll
    for (int off = 16; off > 0; off >>= 1)
        sum += __shfl_xor_sync(0xFFFFFFFFu, sum, off);
    __syncthreads();
    if (lane == 0) sred[wid] = sum;
    __syncthreads();
    float S = sred[0];
#pragma unroll
    for (int w = 1; w < 8; ++w) S += sred[w];
    const float inv = 1.0f / S;

    __half2 hh[4];
#pragma unroll
    for (int p = 0; p < 4; ++p)
        hh[p] = __floats2half2_rn(r[2 * p] * inv, r[2 * p + 1] * inv);
    *(uint4*)(orow + c0) = *(uint4*)hh;
}

// ---------------------------------------------------------------------------
// Launch. t = h@M (k-projection eliminated); MLP in single-fp16 (1-MMA each).
// Stream fork/join as round 12.
// ---------------------------------------------------------------------------
extern "C" void kernel_launch(void* const* d_in, const int* in_sizes, int n_in,
                              void* d_out, int out_size)
{
    (void)in_sizes; (void)n_in; (void)out_size;
    const float* h  = (const float*)d_in[1];
    const float* Wv = (const float*)d_in[2];
    const float* bv = (const float*)d_in[3];
    const float* Wk = (const float*)d_in[4];
    const float* bk = (const float*)d_in[5];
    const float* Wq = (const float*)d_in[6];
    const float* bq = (const float*)d_in[7];
    const float* W1 = (const float*)d_in[8];
    const float* b1 = (const float*)d_in[9];
    const float* W2 = (const float*)d_in[10];
    const float* b2 = (const float*)d_in[11];
    (void)bk;   // row-constant in softmax; drops out
    float* out = (float*)d_out;

    uint8_t *hs, *ts, *v16, *vt16, *o16, *hid16, *wms, *wv16, *w116, *w216;
    float *att, *uvec, *cvec;
    __half* atth;
    cudaGetSymbolAddress((void**)&hs,    g_h_s);
    cudaGetSymbolAddress((void**)&ts,    g_t_s);
    cudaGetSymbolAddress((void**)&v16,   g_v16);
    cudaGetSymbolAddress((void**)&vt16,  g_vt16);
    cudaGetSymbolAddress((void**)&o16,   g_o16);
    cudaGetSymbolAddress((void**)&hid16, g_hid16);
    cudaGetSymbolAddress((void**)&wms,   g_wm_s);
    cudaGetSymbolAddress((void**)&wv16,  g_wv16);
    cudaGetSymbolAddress((void**)&w116,  g_w116);
    cudaGetSymbolAddress((void**)&w216,  g_w216);
    cudaGetSymbolAddress((void**)&att,   g_att);
    cudaGetSymbolAddress((void**)&atth,  g_atth);
    cudaGetSymbolAddress((void**)&uvec,  g_u);
    cudaGetSymbolAddress((void**)&cvec,  g_c);

    static cudaStream_t s1 = nullptr;
    static cudaEvent_t evFork = nullptr, evMt = nullptr, evA = nullptr,
                       evC = nullptr, evLog0 = nullptr, evJoin = nullptr;
    if (!s1) {
        cudaStreamCreateWithFlags(&s1, cudaStreamNonBlocking);
        cudaEventCreateWithFlags(&evFork, cudaEventDisableTiming);
        cudaEventCreateWithFlags(&evMt,   cudaEventDisableTiming);
        cudaEventCreateWithFlags(&evA,    cudaEventDisableTiming);
        cudaEventCreateWithFlags(&evC,    cudaEventDisableTiming);
        cudaEventCreateWithFlags(&evLog0, cudaEventDisableTiming);
        cudaEventCreateWithFlags(&evJoin, cudaEventDisableTiming);
    }

    cudaFuncSetAttribute(hmma_gemm3<false, 1>, cudaFuncAttributeMaxDynamicSharedMemorySize, G3_SMEM);
    cudaFuncSetAttribute(hmma_gemm3<false, 0>, cudaFuncAttributeMaxDynamicSharedMemorySize, G3_SMEM);
    cudaFuncSetAttribute(hmma_gemm2<true, false, 2>, cudaFuncAttributeMaxDynamicSharedMemorySize, G2_SMEM);
    cudaFuncSetAttribute(hmma_gemm1<true,  2>, cudaFuncAttributeMaxDynamicSharedMemorySize, G1_SMEM);
    cudaFuncSetAttribute(hmma_gemm1<false, 0>, cudaFuncAttributeMaxDynamicSharedMemorySize, G1_SMEM);
    cudaFuncSetAttribute(hmma_av1, cudaFuncAttributeMaxDynamicSharedMemorySize, AV_SMEM);

    const dim3 tblk(32, 8), tgrd(16, 16);
    const long long sT    = 2048LL * 2048;   // bytes per batch in t/h split
    const long long sATTf = 2048LL * 2048;   // floats per batch of att
    const int HB = BB / 2;

    // ---- fork s1 immediately ----
    cudaEventRecord(evFork, 0);
    cudaStreamWaitEvent(s1, evFork, 0);

    // s1: Mt = Wk@Wq^T split (needed by t-proj)
    {
        dim3 grd(8, 8);
        wqwk_split<<<grd, 256, 0, s1>>>(Wk, Wq, wms);
    }
    cudaEventRecord(evMt, s1);
    transpose_plain_w16<<<tgrd, tblk, 0, s1>>>(Wv, (__half*)wv16);
    transpose_plain_w16<<<tgrd, tblk, 0, s1>>>(W1, (__half*)w116);
    transpose_plain_w16<<<tgrd, tblk, 0, s1>>>(W2, (__half*)w216);
    compute_u<<<64, 256, 0, s1>>>(Wk, bq, uvec);
    compute_c<<<BN_ROWS / 8, 256, 0, s1>>>(h, uvec, cvec);
    cudaEventRecord(evC, s1);

    // ---- main: h split ----
    split16_rows512<<<(BN_ROWS * 512 / 8) / 256, 256>>>(h, hs);
    cudaEventRecord(evA, 0);

    // s1: v-proj (needs hs) + v^T
    cudaStreamWaitEvent(s1, evA, 0);
    {
        dim3 grd(512 / 128, BN_ROWS / 128, 1);
        hmma_gemm2<true, false, 2><<<grd, 256, G2_SMEM, s1>>>(
            hs, wv16, bv, nullptr, v16, 512, 2048, 1024, 1024);
    }
    {
        dim3 blk(32, 8), grd(16, 64, BB);
        vt_transpose16<<<grd, blk, 0, s1>>>((const __half*)v16, (__half*)vt16);
    }

    // ---- main: t-proj ----
    cudaStreamWaitEvent(0, evMt, 0);
    {
        dim3 grd(512 / 128, BN_ROWS / 128, 1);
        hmma_gemm3<false, 1><<<grd, 256, G3_SMEM>>>(
            hs, wms, nullptr, nullptr, ts, 512, 2048, 2048, 2048, 0, 0, 0);
    }

    // ---- main: logits(H0) = t @ h^T ----
    {
        dim3 grd(NSEQ / 128, NSEQ / 128, HB);
        hmma_gemm3<false, 0><<<grd, 256, G3_SMEM>>>(
            ts, hs, nullptr, att, nullptr,
            512, 2048, 2048, 8192, sT, sT, 2048LL * 8192);
    }
    cudaEventRecord(evLog0, 0);

    // ---- s1: softmax(H0) + AV(H0) ----
    cudaStreamWaitEvent(s1, evLog0, 0);
    softmax_f16_kernel<<<HB * NSEQ, 256, 0, s1>>>(att, atth, cvec);
    {
        dim3 grd(512 / 128, NSEQ / 128, HB);
        hmma_av1<<<grd, 256, AV_SMEM, s1>>>((const uint8_t*)atth, vt16, o16);
    }
    cudaEventRecord(evJoin, s1);

    // ---- main: logits(H1), softmax(H1), AV(H1) ----
    {
        dim3 grd(NSEQ / 128, NSEQ / 128, HB);
        hmma_gemm3<false, 0><<<grd, 256, G3_SMEM>>>(
            ts + HB * sT, hs + HB * sT, nullptr,
            att + HB * sATTf, nullptr,
            512, 2048, 2048, 8192, sT, sT, 2048LL * 8192);
    }
    cudaStreamWaitEvent(0, evC, 0);
    softmax_f16_kernel<<<HB * NSEQ, 256>>>(att + HB * sATTf, atth + HB * sATTf,
                                           cvec + (long long)HB * NSEQ);
    cudaStreamWaitEvent(0, evJoin, 0);
    {
        dim3 grd(512 / 128, NSEQ / 128, HB);
        hmma_av1<<<grd, 256, AV_SMEM>>>(
            (const uint8_t*)(atth + HB * sATTf),
            vt16 + (long long)HB * 512 * 4096,
            o16 + (long long)HB * 2048 * 1024);
    }

    // ---- MLP (1-MMA each, plain fp16 operands) ----
    {
        dim3 grd(512 / 128, BN_ROWS / 128, 1);
        hmma_gemm1<true,  2><<<grd, 256, G1_SMEM>>>(
            o16, w116, b1, nullptr, hid16, 512, 1024, 1024, 1024);
        hmma_gemm1<false, 0><<<grd, 256, G1_SMEM>>>(
            hid16, w216, b2, out, nullptr, 512, 1024, 1024, 2048);
    }
}

// round 14
// speedup vs baseline: 1.2877x; 1.0752x over previous
#include <cuda_runtime.h>
#include <cuda_fp16.h>
#include <math.h>
#include <stdint.h>

// Problem dims (fixed)
#define BB 16
#define NSEQ 2048
#define MM 512
#define HH 512
#define BN_ROWS (BB * NSEQ)   // 32768

// ---------------------------------------------------------------------------
// Split layout (fp16): 4 bytes/elem, groups of 32 cols: 128B = 32 hi | 32 lo.
// byte(r, c) = r*rowBytes + (c>>5)*128 + (c&31)*2   (hi; lo at +64)
// Plain fp16 layout: byte(r, c) = r*rowBytes + c*2.
// ---------------------------------------------------------------------------
__device__ __align__(128) uint8_t g_h_s  [(long long)BN_ROWS * HH * 4];     // h split
__device__ __align__(128) uint8_t g_h16  [(long long)BN_ROWS * HH * 2];     // h plain
__device__ __align__(128) uint8_t g_t_s  [(long long)BN_ROWS * HH * 4];     // t = h@M split
__device__ __align__(128) uint8_t g_v16  [(long long)BN_ROWS * HH * 2];     // v plain
__device__ __align__(128) uint8_t g_vt16 [(long long)BN_ROWS * HH * 2];     // v^T plain
__device__ __align__(128) uint8_t g_o16  [(long long)BN_ROWS * HH * 2];     // o plain
__device__ __align__(128) uint8_t g_hid16[(long long)BN_ROWS * HH * 2];     // hid plain
__device__ __align__(128) uint8_t g_wm_s [512LL * 512 * 4];                 // M^T = Wk@Wq^T split
__device__ __align__(128) uint8_t g_wv16 [512LL * 512 * 2];                 // Wv^T plain
__device__ __align__(128) uint8_t g_w116 [512LL * 512 * 2];                 // W1^T plain
__device__ __align__(128) uint8_t g_w216 [512LL * 512 * 2];                 // W2^T plain
__device__ float g_att[(long long)BB * NSEQ * NSEQ];
__device__ __align__(128) __half g_atth[(long long)BB * NSEQ * NSEQ];
__device__ float g_u[512];            // Wk @ bq
__device__ float g_c[BN_ROWS];        // per-column softmax bias c_j = h_j . u

// ---------------------------------------------------------------------------
// Helpers
// ---------------------------------------------------------------------------
__device__ __forceinline__ uint32_t smem_u32(const void* p) {
    uint32_t a;
    asm("{ .reg .u64 t; cvta.to.shared.u64 t, %1; cvt.u32.u64 %0, t; }" : "=r"(a) : "l"(p));
    return a;
}
__device__ __forceinline__ void ldsm4(uint32_t* r, uint32_t addr) {
    asm volatile("ldmatrix.sync.aligned.m8n8.x4.shared.b16 {%0,%1,%2,%3}, [%4];"
                 : "=r"(r[0]), "=r"(r[1]), "=r"(r[2]), "=r"(r[3]) : "r"(addr));
}
__device__ __forceinline__ void mma_f16(float* c, const uint32_t* a,
                                        uint32_t b0, uint32_t b1) {
    asm volatile(
        "mma.sync.aligned.m16n8k16.row.col.f32.f16.f16.f32 "
        "{%0,%1,%2,%3}, {%4,%5,%6,%7}, {%8,%9}, {%0,%1,%2,%3};"
        : "+f"(c[0]), "+f"(c[1]), "+f"(c[2]), "+f"(c[3])
        : "r"(a[0]), "r"(a[1]), "r"(a[2]), "r"(a[3]), "r"(b0), "r"(b1));
}
__device__ __forceinline__ void cp16(uint32_t dst, const void* src) {
    asm volatile("cp.async.cg.shared.global [%0], [%1], 16;" :: "r"(dst), "l"(src));
}
__device__ __forceinline__ void cp_commit() {
    asm volatile("cp.async.commit_group;");
}
template <int N> __device__ __forceinline__ void cp_wait() {
    asm volatile("cp.async.wait_group %0;" :: "n"(N));
}
__device__ __forceinline__ void split2h(float x, float y, uint32_t& hi, uint32_t& lo) {
    __half2 h = __floats2half2_rn(x, y);
    __half2 l = __floats2half2_rn(x - __half2float(h.x), y - __half2float(h.y));
    hi = *(uint32_t*)&h;
    lo = *(uint32_t*)&l;
}

// Plain-fp16 smem tile addressing (64B data per row, 2 rows per 128B line,
// 8-chunk XOR swizzle): conflict-free for ldmatrix and cp.async.
__device__ __forceinline__ uint32_t plainb_addr(uint32_t base, int r, int c) {
    return base + ((r >> 1) << 7) + (((((r & 1) << 2) + c) ^ ((r >> 1) & 7)) << 4);
}

// OUTMODE: 0 = fp32, 1 = split fp16, 2 = plain fp16

// ---------------------------------------------------------------------------
// gemm3: A split, B split, 3 MMAs, chain-batched. CTA 128x128, warp 32x64.
// ---------------------------------------------------------------------------
#define G3_STAGES 3
#define G3_STAGE 32768
#define G3_SMEM (G3_STAGES * G3_STAGE)

template <bool HAS_BIAS, int OUTMODE>
__global__ __launch_bounds__(256, 2)
void hmma_gemm3(const uint8_t* __restrict__ A, const uint8_t* __restrict__ B,
                const float* __restrict__ bias, float* __restrict__ Cf,
                uint8_t* __restrict__ Cs,
                int K, long long ldaB, long long ldbB, long long ldcB,
                long long sA, long long sB, long long sC)
{
    extern __shared__ uint8_t sm[];
    const long long bz = blockIdx.z;
    A += bz * sA;
    B += bz * sB;

    const int tid = threadIdx.x;
    const int wid = tid >> 5, lane = tid & 31;
    const int wm = wid & 3, wn = wid >> 2;
    const int lr = lane & 15, lc = lane >> 4;
    const int m0 = blockIdx.y * 128, n0 = blockIdx.x * 128;

    const int lrow = tid >> 1;
    const int cb = (tid & 1) * 4;
    const int rsw = lrow & 7;

    const uint32_t smb = smem_u32(sm);
    const uint8_t* srcA0 = A + (long long)(m0 + lrow) * ldaB + cb * 16;
    const uint8_t* srcB0 = B + (long long)(n0 + lrow) * ldbB + cb * 16;

    float acc[2][8][4];
#pragma unroll
    for (int i = 0; i < 2; ++i)
#pragma unroll
        for (int j = 0; j < 8; ++j)
#pragma unroll
            for (int t = 0; t < 4; ++t) acc[i][j][t] = 0.0f;

    const int S = K / 32;

#define G3_ISSUE(s)                                                           \
    do {                                                                      \
        const uint32_t dra = smb + ((s) % G3_STAGES) * G3_STAGE + lrow * 128; \
        const uint8_t* pa = srcA0 + (s) * 128;                                \
        const uint8_t* pb = srcB0 + (s) * 128;                                \
        _Pragma("unroll")                                                     \
        for (int c = 0; c < 4; ++c)                                           \
            cp16(dra + (((cb + c) ^ rsw) << 4), pa + c * 16);                 \
        _Pragma("unroll")                                                     \
        for (int c = 0; c < 4; ++c)                                           \
            cp16(dra + 16384 + (((cb + c) ^ rsw) << 4), pb + c * 16);         \
        cp_commit();                                                          \
    } while (0)

    G3_ISSUE(0);
    G3_ISSUE(1);

    for (int s = 0; s < S; ++s) {
        if (s + 1 < S) cp_wait<1>(); else cp_wait<0>();
        __syncthreads();
        if (s + 2 < S) G3_ISSUE(s + 2);

        const uint32_t bufA = smb + (s % G3_STAGES) * G3_STAGE;
        const uint32_t bufB = bufA + 16384;

#pragma unroll
        for (int kk = 0; kk < 2; ++kk) {
            uint32_t aH[2][4], aL[2][4];
            const int byteh = kk * 32 + lc * 16;
#pragma unroll
            for (int mi = 0; mi < 2; ++mi) {
                const int r = wm * 32 + mi * 16 + lr;
                const uint32_t rb = bufA + r * 128;
                const int rs = r & 7;
                ldsm4(aH[mi], rb + ((((byteh) >> 4) ^ rs) << 4));
                ldsm4(aL[mi], rb + ((((byteh + 64) >> 4) ^ rs) << 4));
            }
#pragma unroll
            for (int g = 0; g < 4; ++g) {
                const int r = wn * 64 + g * 16 + lr;
                const uint32_t rb = bufB + r * 128;
                const int rs = r & 7;
                uint32_t bh[4], bl[4];
                ldsm4(bh, rb + ((((byteh) >> 4) ^ rs) << 4));
                ldsm4(bl, rb + ((((byteh + 64) >> 4) ^ rs) << 4));
#pragma unroll
                for (int mi = 0; mi < 2; ++mi) {          // HH
                    mma_f16(acc[mi][2 * g],     aH[mi], bh[0], bh[2]);
                    mma_f16(acc[mi][2 * g + 1], aH[mi], bh[1], bh[3]);
                }
#pragma unroll
                for (int mi = 0; mi < 2; ++mi) {          // HL
                    mma_f16(acc[mi][2 * g],     aH[mi], bl[0], bl[2]);
                    mma_f16(acc[mi][2 * g + 1], aH[mi], bl[1], bl[3]);
                }
#pragma unroll
                for (int mi = 0; mi < 2; ++mi) {          // LH
                    mma_f16(acc[mi][2 * g],     aL[mi], bh[0], bh[2]);
                    mma_f16(acc[mi][2 * g + 1], aL[mi], bh[1], bh[3]);
                }
            }
        }
    }
#undef G3_ISSUE

#pragma unroll
    for (int mi = 0; mi < 2; ++mi) {
        const long long r0 = m0 + wm * 32 + mi * 16 + (lane >> 2);
#pragma unroll
        for (int nj = 0; nj < 8; ++nj) {
            const int col = n0 + wn * 64 + nj * 8 + 2 * (lane & 3);
            float bx = 0.0f, by = 0.0f;
            if (HAS_BIAS) {
                const float2 bvv = *(const float2*)(bias + col);
                bx = bvv.x; by = bvv.y;
            }
            const float x0 = acc[mi][nj][0] + bx;
            const float x1 = acc[mi][nj][1] + by;
            const float x2 = acc[mi][nj][2] + bx;
            const float x3 = acc[mi][nj][3] + by;
            if (OUTMODE == 0) {
                uint8_t* base = (uint8_t*)Cf + bz * sC;
                *(float2*)(base + r0 * ldcB + col * 4)       = make_float2(x0, x1);
                *(float2*)(base + (r0 + 8) * ldcB + col * 4) = make_float2(x2, x3);
            } else {
                uint8_t* base = Cs + bz * sC;
                const long long cb0 = (long long)(col >> 5) * 128 + (col & 31) * 2;
                uint32_t hi, lo;
                split2h(x0, x1, hi, lo);
                uint8_t* p = base + r0 * ldcB + cb0;
                *(uint32_t*)p = hi;
                *(uint32_t*)(p + 64) = lo;
                split2h(x2, x3, hi, lo);
                p = base + (r0 + 8) * ldcB + cb0;
                *(uint32_t*)p = hi;
                *(uint32_t*)(p + 64) = lo;
            }
        }
    }
}

// ---------------------------------------------------------------------------
// gemm1: A plain fp16, B plain fp16, 1 MMA, +bias, optional relu.
// OUTMODE 0 = fp32 out, 2 = plain fp16 out. (v-proj and MLP.)
// ---------------------------------------------------------------------------
#define G1_STAGES 4
#define G1_STAGE 16384
#define G1_SMEM (G1_STAGES * G1_STAGE)

template <bool RELU, int OUTMODE>
__global__ __launch_bounds__(256, 2)
void hmma_gemm1(const uint8_t* __restrict__ A, const uint8_t* __restrict__ B,
                const float* __restrict__ bias, float* __restrict__ Cf,
                uint8_t* __restrict__ Cs,
                int K, long long ldaB, long long ldbB, long long ldcB)
{
    extern __shared__ uint8_t sm[];
    const int tid = threadIdx.x;
    const int wid = tid >> 5, lane = tid & 31;
    const int wm = wid & 3, wn = wid >> 2;
    const int lr = lane & 15, lc = lane >> 4;
    const int m0 = blockIdx.y * 128, n0 = blockIdx.x * 128;

    const int lrow = tid >> 1;
    const int cb2 = (tid & 1) * 2;

    const uint32_t smb = smem_u32(sm);
    const uint8_t* srcA0 = A + (long long)(m0 + lrow) * ldaB + cb2 * 16;
    const uint8_t* srcB0 = B + (long long)(n0 + lrow) * ldbB + cb2 * 16;

    float acc[2][8][4];
#pragma unroll
    for (int i = 0; i < 2; ++i)
#pragma unroll
        for (int j = 0; j < 8; ++j)
#pragma unroll
            for (int t = 0; t < 4; ++t) acc[i][j][t] = 0.0f;

    const int S = K / 32;

#define G1_ISSUE(s)                                                           \
    do {                                                                      \
        const uint32_t stb = smb + ((s) % G1_STAGES) * G1_STAGE;              \
        const uint8_t* pa = srcA0 + (s) * 64;                                 \
        const uint8_t* pb = srcB0 + (s) * 64;                                 \
        _Pragma("unroll")                                                     \
        for (int c = 0; c < 2; ++c)                                           \
            cp16(plainb_addr(stb, lrow, cb2 + c), pa + c * 16);               \
        _Pragma("unroll")                                                     \
        for (int c = 0; c < 2; ++c)                                           \
            cp16(plainb_addr(stb + 8192, lrow, cb2 + c), pb + c * 16);        \
        cp_commit();                                                          \
    } while (0)

    G1_ISSUE(0);
    G1_ISSUE(1);
    G1_ISSUE(2);

    for (int s = 0; s < S; ++s) {
        if (s + 1 < S) cp_wait<2>(); else cp_wait<0>();
        __syncthreads();
        if (s + 3 < S) G1_ISSUE(s + 3);

        const uint32_t bufA = smb + (s % G1_STAGES) * G1_STAGE;
        const uint32_t bufB = bufA + 8192;

#pragma unroll
        for (int kk = 0; kk < 2; ++kk) {
            const int c = kk * 2 + lc;
            uint32_t aF[2][4];
#pragma unroll
            for (int mi = 0; mi < 2; ++mi) {
                const int r = wm * 32 + mi * 16 + lr;
                ldsm4(aF[mi], plainb_addr(bufA, r, c));
            }
#pragma unroll
            for (int g = 0; g < 4; ++g) {
                const int r = wn * 64 + g * 16 + lr;
                uint32_t b[4];
                ldsm4(b, plainb_addr(bufB, r, c));
#pragma unroll
                for (int mi = 0; mi < 2; ++mi) {
                    mma_f16(acc[mi][2 * g],     aF[mi], b[0], b[2]);
                    mma_f16(acc[mi][2 * g + 1], aF[mi], b[1], b[3]);
                }
            }
        }
    }
#undef G1_ISSUE

#pragma unroll
    for (int mi = 0; mi < 2; ++mi) {
        const long long r0 = m0 + wm * 32 + mi * 16 + (lane >> 2);
#pragma unroll
        for (int nj = 0; nj < 8; ++nj) {
            const int col = n0 + wn * 64 + nj * 8 + 2 * (lane & 3);
            const float2 bvv = *(const float2*)(bias + col);
            float x0 = acc[mi][nj][0] + bvv.x;
            float x1 = acc[mi][nj][1] + bvv.y;
            float x2 = acc[mi][nj][2] + bvv.x;
            float x3 = acc[mi][nj][3] + bvv.y;
            if (RELU) {
                x0 = fmaxf(x0, 0.0f); x1 = fmaxf(x1, 0.0f);
                x2 = fmaxf(x2, 0.0f); x3 = fmaxf(x3, 0.0f);
            }
            if (OUTMODE == 0) {
                *(float2*)((uint8_t*)Cf + r0 * ldcB + col * 4)       = make_float2(x0, x1);
                *(float2*)((uint8_t*)Cf + (r0 + 8) * ldcB + col * 4) = make_float2(x2, x3);
            } else {
                __half2 v01 = __floats2half2_rn(x0, x1);
                __half2 v23 = __floats2half2_rn(x2, x3);
                *(uint32_t*)(Cs + r0 * ldcB + col * 2)       = *(uint32_t*)&v01;
                *(uint32_t*)(Cs + (r0 + 8) * ldcB + col * 2) = *(uint32_t*)&v23;
            }
        }
    }
}

// ---------------------------------------------------------------------------
// av1: o[b] = att[b] @ vt[b]^T; both plain fp16, 1 MMA. Out: o plain fp16.
// ---------------------------------------------------------------------------
#define AV_STAGES 4
#define AV_STAGE 16384
#define AV_SMEM (AV_STAGES * AV_STAGE)

__global__ __launch_bounds__(256, 2)
void hmma_av1(const uint8_t* __restrict__ A, const uint8_t* __restrict__ B,
              uint8_t* __restrict__ Cs)
{
    extern __shared__ uint8_t sm[];
    const long long bz = blockIdx.z;
    A += bz * (long long)NSEQ * 4096;       // att rows, 2048 fp16
    B += bz * 512LL * 4096;                 // vt rows, 2048 fp16

    const int tid = threadIdx.x;
    const int wid = tid >> 5, lane = tid & 31;
    const int wm = wid & 3, wn = wid >> 2;
    const int lr = lane & 15, lc = lane >> 4;
    const int m0 = blockIdx.y * 128, n0 = blockIdx.x * 128;

    const int lrow = tid >> 1;
    const int cb2 = (tid & 1) * 2;

    const uint32_t smb = smem_u32(sm);
    const uint8_t* srcA0 = A + (long long)(m0 + lrow) * 4096 + cb2 * 16;
    const uint8_t* srcB0 = B + (long long)(n0 + lrow) * 4096 + cb2 * 16;

    float acc[2][8][4];
#pragma unroll
    for (int i = 0; i < 2; ++i)
#pragma unroll
        for (int j = 0; j < 8; ++j)
#pragma unroll
            for (int t = 0; t < 4; ++t) acc[i][j][t] = 0.0f;

    const int S = NSEQ / 32;  // 64

#define AV_ISSUE(s)                                                           \
    do {                                                                      \
        const uint32_t stb = smb + ((s) % AV_STAGES) * AV_STAGE;              \
        const uint8_t* pa = srcA0 + (s) * 64;                                 \
        const uint8_t* pb = srcB0 + (s) * 64;                                 \
        _Pragma("unroll")                                                     \
        for (int c = 0; c < 2; ++c)                                           \
            cp16(plainb_addr(stb, lrow, cb2 + c), pa + c * 16);               \
        _Pragma("unroll")                                                     \
        for (int c = 0; c < 2; ++c)                                           \
            cp16(plainb_addr(stb + 8192, lrow, cb2 + c), pb + c * 16);        \
        cp_commit();                                                          \
    } while (0)

    AV_ISSUE(0);
    AV_ISSUE(1);
    AV_ISSUE(2);

    for (int s = 0; s < S; ++s) {
        if (s + 1 < S) cp_wait<2>(); else cp_wait<0>();
        __syncthreads();
        if (s + 3 < S) AV_ISSUE(s + 3);

        const uint32_t bufA = smb + (s % AV_STAGES) * AV_STAGE;
        const uint32_t bufB = bufA + 8192;

#pragma unroll
        for (int kk = 0; kk < 2; ++kk) {
            const int c = kk * 2 + lc;
            uint32_t aF[2][4];
#pragma unroll
            for (int mi = 0; mi < 2; ++mi) {
                const int r = wm * 32 + mi * 16 + lr;
                ldsm4(aF[mi], plainb_addr(bufA, r, c));
            }
#pragma unroll
            for (int g = 0; g < 4; ++g) {
                const int r = wn * 64 + g * 16 + lr;
                uint32_t b[4];
                ldsm4(b, plainb_addr(bufB, r, c));
#pragma unroll
                for (int mi = 0; mi < 2; ++mi) {
                    mma_f16(acc[mi][2 * g],     aF[mi], b[0], b[2]);
                    mma_f16(acc[mi][2 * g + 1], aF[mi], b[1], b[3]);
                }
            }
        }
    }
#undef AV_ISSUE

#pragma unroll
    for (int mi = 0; mi < 2; ++mi) {
        const long long r0 = bz * NSEQ + m0 + wm * 32 + mi * 16 + (lane >> 2);
#pragma unroll
        for (int nj = 0; nj < 8; ++nj) {
            const int col = n0 + wn * 64 + nj * 8 + 2 * (lane & 3);
            __half2 v01 = __floats2half2_rn(acc[mi][nj][0], acc[mi][nj][1]);
            __half2 v23 = __floats2half2_rn(acc[mi][nj][2], acc[mi][nj][3]);
            *(uint32_t*)(Cs + r0 * 1024 + col * 2)       = *(uint32_t*)&v01;
            *(uint32_t*)(Cs + (r0 + 8) * 1024 + col * 2) = *(uint32_t*)&v23;
        }
    }
}

// ---------------------------------------------------------------------------
// Mt = Wk @ Wq^T (fp32 tiled SIMT), output split fp16 [512 rows x 2048B].
// ---------------------------------------------------------------------------
__global__ __launch_bounds__(256)
void wqwk_split(const float* __restrict__ Wk, const float* __restrict__ Wq,
                uint8_t* __restrict__ out)
{
    __shared__ float sk[64][36], sq[64][36];
    const int b0 = blockIdx.y * 64;
    const int a0 = blockIdx.x * 64;
    const int tid = threadIdx.x;
    const int ty = tid >> 4, tx = tid & 15;

    float acc[4][4];
#pragma unroll
    for (int i = 0; i < 4; ++i)
#pragma unroll
        for (int j = 0; j < 4; ++j) acc[i][j] = 0.0f;

    const int lr = tid >> 2;
    const int lcb = (tid & 3) * 8;

    for (int k0 = 0; k0 < 512; k0 += 32) {
        *(float4*)&sk[lr][lcb]     = *(const float4*)(Wk + (long long)(b0 + lr) * 512 + k0 + lcb);
        *(float4*)&sk[lr][lcb + 4] = *(const float4*)(Wk + (long long)(b0 + lr) * 512 + k0 + lcb + 4);
        *(float4*)&sq[lr][lcb]     = *(const float4*)(Wq + (long long)(a0 + lr) * 512 + k0 + lcb);
        *(float4*)&sq[lr][lcb + 4] = *(const float4*)(Wq + (long long)(a0 + lr) * 512 + k0 + lcb + 4);
        __syncthreads();
#pragma unroll 8
        for (int kk = 0; kk < 32; ++kk)
#pragma unroll
            for (int i = 0; i < 4; ++i)
#pragma unroll
                for (int j = 0; j < 4; ++j)
                    acc[i][j] = fmaf(sk[ty * 4 + i][kk], sq[tx * 4 + j][kk], acc[i][j]);
        __syncthreads();
    }

#pragma unroll
    for (int i = 0; i < 4; ++i) {
        const int b = b0 + ty * 4 + i;
#pragma unroll
        for (int jp = 0; jp < 2; ++jp) {
            const int a = a0 + tx * 4 + jp * 2;
            uint32_t hi, lo;
            split2h(acc[i][jp * 2], acc[i][jp * 2 + 1], hi, lo);
            uint8_t* p = out + (long long)b * 2048 + (a >> 5) * 128 + (a & 31) * 2;
            *(uint32_t*)p = hi;
            *(uint32_t*)(p + 64) = lo;
        }
    }
}

// u[m] = sum_h Wk[m,h] * bq[h].  One warp per m.
__global__ __launch_bounds__(256)
void compute_u(const float* __restrict__ Wk, const float* __restrict__ bq,
               float* __restrict__ u)
{
    const int w = (blockIdx.x * 256 + threadIdx.x) >> 5;
    const int lane = threadIdx.x & 31;
    if (w >= 512) return;
    const float* row = Wk + (long long)w * 512;
    float s = 0.0f;
    for (int h = lane; h < 512; h += 32) s += row[h] * bq[h];
#pragma unroll
    for (int off = 16; off > 0; off >>= 1)
        s += __shfl_xor_sync(0xFFFFFFFFu, s, off);
    if (lane == 0) u[w] = s;
}

// c[i] = sum_m h[i,m] * u[m].  One warp per row.
__global__ __launch_bounds__(256)
void compute_c(const float* __restrict__ h, const float* __restrict__ u,
               float* __restrict__ c)
{
    const long long w = ((long long)blockIdx.x * 256 + threadIdx.x) >> 5;
    const int lane = threadIdx.x & 31;
    const float* row = h + w * 512;
    float s = 0.0f;
    for (int m = lane; m < 512; m += 32) s += row[m] * u[m];
#pragma unroll
    for (int off = 16; off > 0; off >>= 1)
        s += __shfl_xor_sync(0xFFFFFFFFu, s, off);
    if (lane == 0) c[w] = s;
}

// ---------------------------------------------------------------------------
// Prep: h -> split fp16 AND plain fp16.
// ---------------------------------------------------------------------------
__global__ __launch_bounds__(256)
void split16_rows512(const float* __restrict__ in, uint8_t* __restrict__ out,
                     uint8_t* __restrict__ out16)
{
    const long long i8 = ((long long)blockIdx.x * 256 + threadIdx.x) * 8;
    const long long row = i8 >> 9;
    const int col = (int)(i8 & 511);
    const float4 a = *(const float4*)(in + i8);
    const float4 b = *(const float4*)(in + i8 + 4);
    uint4 hi, lo;
    split2h(a.x, a.y, hi.x, lo.x);
    split2h(a.z, a.w, hi.y, lo.y);
    split2h(b.x, b.y, hi.z, lo.z);
    split2h(b.z, b.w, hi.w, lo.w);
    uint8_t* p = out + row * 2048 + (col >> 5) * 128 + (col & 31) * 2;
    *(uint4*)p = hi;
    *(uint4*)(p + 64) = lo;
    *(uint4*)(out16 + row * 1024 + col * 2) = hi;   // plain fp16 copy
}

__global__ __launch_bounds__(256)
void transpose_plain_w16(const float* __restrict__ in, __half* __restrict__ out)
{
    __shared__ float t[32][33];
    const int c0 = blockIdx.x * 32;
    const int r0 = blockIdx.y * 32;
    const int x = threadIdx.x;
    const int y = threadIdx.y;
#pragma unroll
    for (int j = 0; j < 32; j += 8)
        t[y + j][x] = in[(long long)(r0 + y + j) * 512 + c0 + x];
    __syncthreads();
#pragma unroll
    for (int j = 0; j < 32; j += 8)
        out[(long long)(c0 + y + j) * 512 + r0 + x] = __float2half_rn(t[x][y + j]);
}

__global__ __launch_bounds__(256)
void vt_transpose16(const __half* __restrict__ v, __half* __restrict__ vt)
{
    __shared__ __half t[32][33];
    const long long b = blockIdx.z;
    const int h0 = blockIdx.x * 32;
    const int n0 = blockIdx.y * 32;
    const int x = threadIdx.x;
    const int y = threadIdx.y;
#pragma unroll
    for (int j = 0; j < 32; j += 8)
        t[y + j][x] = v[(b * 2048 + n0 + y + j) * 512 + h0 + x];
    __syncthreads();
#pragma unroll
    for (int j = 0; j < 32; j += 8)
        vt[b * 512 * 2048 + (long long)(h0 + y + j) * 2048 + n0 + x] = t[x][y + j];
}

// ---------------------------------------------------------------------------
// Row softmax (2048) fp32 -> fp16 with per-column bias c_j, gated exp.
// ---------------------------------------------------------------------------
__global__ __launch_bounds__(256)
void softmax_f16_kernel(const float* __restrict__ att, __half* __restrict__ outh,
                        const float* __restrict__ cvec)
{
    const float* row = att + (long long)blockIdx.x * NSEQ;
    __half* orow = outh + (long long)blockIdx.x * NSEQ;
    const float* cb = cvec + (((long long)blockIdx.x >> 11) << 11);
    __shared__ float sred[8];
    const int tid = threadIdx.x;
    const int wid = tid >> 5;
    const int lane = tid & 31;
    const int c0 = tid * 8;

    float r[8];
    *(float4*)&r[0] = *(const float4*)(row + c0);
    *(float4*)&r[4] = *(const float4*)(row + c0 + 4);
    float cv[8];
    *(float4*)&cv[0] = *(const float4*)(cb + c0);
    *(float4*)&cv[4] = *(const float4*)(cb + c0 + 4);
#pragma unroll
    for (int p = 0; p < 8; ++p) r[p] += cv[p];

    float lmax = r[0];
#pragma unroll
    for (int p = 1; p < 8; ++p) lmax = fmaxf(lmax, r[p]);
    float m = lmax;
#pragma unroll
    for (int off = 16; off > 0; off >>= 1)
        m = fmaxf(m, __shfl_xor_sync(0xFFFFFFFFu, m, off));
    if (lane == 0) sred[wid] = m;
    __syncthreads();
    float M = sred[0];
#pragma unroll
    for (int w = 1; w < 8; ++w) M = fmaxf(M, sred[w]);

    float sum = 0.0f;
    if (lmax - M > -25.0f) {
#pragma unroll
        for (int p = 0; p < 8; ++p) {
            r[p] = __expf(r[p] - M);
            sum += r[p];
        }
    } else {
#pragma unroll
        for (int p = 0; p < 8; ++p) r[p] = 0.0f;
    }

#pragma unroll
    for (int off = 16; off > 0; off >>= 1)
        sum += __shfl_xor_sync(0xFFFFFFFFu, sum, off);
    __syncthreads();
    if (lane == 0) sred[wid] = sum;
    __syncthreads();
    float S = sred[0];
#pragma unroll
    for (int w = 1; w < 8; ++w) S += sred[w];
    const float inv = 1.0f / S;

    __half2 hh[4];
#pragma unroll
    for (int p = 0; p < 4; ++p)
        hh[p] = __floats2half2_rn(r[2 * p] * inv, r[2 * p + 1] * inv);
    *(uint4*)(orow + c0) = *(uint4*)hh;
}

// ---------------------------------------------------------------------------
// Launch. t = h@M (k-proj eliminated); v-proj + MLP single-fp16 1-MMA;
// MLP split by row-halves across streams (MLP(H0) on s1 under logits(H1)).
// ---------------------------------------------------------------------------
extern "C" void kernel_launch(void* const* d_in, const int* in_sizes, int n_in,
                              void* d_out, int out_size)
{
    (void)in_sizes; (void)n_in; (void)out_size;
    const float* h  = (const float*)d_in[1];
    const float* Wv = (const float*)d_in[2];
    const float* bv = (const float*)d_in[3];
    const float* Wk = (const float*)d_in[4];
    const float* bk = (const float*)d_in[5];
    const float* Wq = (const float*)d_in[6];
    const float* bq = (const float*)d_in[7];
    const float* W1 = (const float*)d_in[8];
    const float* b1 = (const float*)d_in[9];
    const float* W2 = (const float*)d_in[10];
    const float* b2 = (const float*)d_in[11];
    (void)bk;   // row-constant in softmax; drops out
    float* out = (float*)d_out;

    uint8_t *hs, *h16, *ts, *v16, *vt16, *o16, *hid16, *wms, *wv16, *w116, *w216;
    float *att, *uvec, *cvec;
    __half* atth;
    cudaGetSymbolAddress((void**)&hs,    g_h_s);
    cudaGetSymbolAddress((void**)&h16,   g_h16);
    cudaGetSymbolAddress((void**)&ts,    g_t_s);
    cudaGetSymbolAddress((void**)&v16,   g_v16);
    cudaGetSymbolAddress((void**)&vt16,  g_vt16);
    cudaGetSymbolAddress((void**)&o16,   g_o16);
    cudaGetSymbolAddress((void**)&hid16, g_hid16);
    cudaGetSymbolAddress((void**)&wms,   g_wm_s);
    cudaGetSymbolAddress((void**)&wv16,  g_wv16);
    cudaGetSymbolAddress((void**)&w116,  g_w116);
    cudaGetSymbolAddress((void**)&w216,  g_w216);
    cudaGetSymbolAddress((void**)&att,   g_att);
    cudaGetSymbolAddress((void**)&atth,  g_atth);
    cudaGetSymbolAddress((void**)&uvec,  g_u);
    cudaGetSymbolAddress((void**)&cvec,  g_c);

    static cudaStream_t s1 = nullptr;
    static cudaEvent_t evFork = nullptr, evMt = nullptr, evA = nullptr,
                       evC = nullptr, evVt = nullptr, evLog0 = nullptr,
                       evJoin = nullptr;
    if (!s1) {
        cudaStreamCreateWithFlags(&s1, cudaStreamNonBlocking);
        cudaEventCreateWithFlags(&evFork, cudaEventDisableTiming);
        cudaEventCreateWithFlags(&evMt,   cudaEventDisableTiming);
        cudaEventCreateWithFlags(&evA,    cudaEventDisableTiming);
        cudaEventCreateWithFlags(&evC,    cudaEventDisableTiming);
        cudaEventCreateWithFlags(&evVt,   cudaEventDisableTiming);
        cudaEventCreateWithFlags(&evLog0, cudaEventDisableTiming);
        cudaEventCreateWithFlags(&evJoin, cudaEventDisableTiming);
    }

    cudaFuncSetAttribute(hmma_gemm3<false, 1>, cudaFuncAttributeMaxDynamicSharedMemorySize, G3_SMEM);
    cudaFuncSetAttribute(hmma_gemm3<false, 0>, cudaFuncAttributeMaxDynamicSharedMemorySize, G3_SMEM);
    cudaFuncSetAttribute(hmma_gemm1<false, 2>, cudaFuncAttributeMaxDynamicSharedMemorySize, G1_SMEM);
    cudaFuncSetAttribute(hmma_gemm1<true,  2>, cudaFuncAttributeMaxDynamicSharedMemorySize, G1_SMEM);
    cudaFuncSetAttribute(hmma_gemm1<false, 0>, cudaFuncAttributeMaxDynamicSharedMemorySize, G1_SMEM);
    cudaFuncSetAttribute(hmma_av1, cudaFuncAttributeMaxDynamicSharedMemorySize, AV_SMEM);

    const dim3 tblk(32, 8), tgrd(16, 16);
    const long long sT    = 2048LL * 2048;   // bytes per batch in t/h split
    const long long sATTf = 2048LL * 2048;   // floats per batch of att
    const int HB = BB / 2;
    const long long hbRows = (long long)HB * NSEQ;   // 16384

    // ---- fork s1 immediately ----
    cudaEventRecord(evFork, 0);
    cudaStreamWaitEvent(s1, evFork, 0);

    // s1: Mt = Wk@Wq^T split
    {
        dim3 grd(8, 8);
        wqwk_split<<<grd, 256, 0, s1>>>(Wk, Wq, wms);
    }
    cudaEventRecord(evMt, s1);
    transpose_plain_w16<<<tgrd, tblk, 0, s1>>>(Wv, (__half*)wv16);
    transpose_plain_w16<<<tgrd, tblk, 0, s1>>>(W1, (__half*)w116);
    transpose_plain_w16<<<tgrd, tblk, 0, s1>>>(W2, (__half*)w216);
    compute_u<<<64, 256, 0, s1>>>(Wk, bq, uvec);
    compute_c<<<BN_ROWS / 8, 256, 0, s1>>>(h, uvec, cvec);
    cudaEventRecord(evC, s1);

    // ---- main: h split + plain ----
    split16_rows512<<<(BN_ROWS * 512 / 8) / 256, 256>>>(h, hs, h16);
    cudaEventRecord(evA, 0);

    // s1: v-proj (1-MMA plain) + v^T
    cudaStreamWaitEvent(s1, evA, 0);
    {
        dim3 grd(512 / 128, BN_ROWS / 128, 1);
        hmma_gemm1<false, 2><<<grd, 256, G1_SMEM, s1>>>(
            h16, wv16, bv, nullptr, v16, 512, 1024, 1024, 1024);
    }
    {
        dim3 blk(32, 8), grd(16, 64, BB);
        vt_transpose16<<<grd, blk, 0, s1>>>((const __half*)v16, (__half*)vt16);
    }
    cudaEventRecord(evVt, s1);

    // ---- main: t-proj ----
    cudaStreamWaitEvent(0, evMt, 0);
    {
        dim3 grd(512 / 128, BN_ROWS / 128, 1);
        hmma_gemm3<false, 1><<<grd, 256, G3_SMEM>>>(
            hs, wms, nullptr, nullptr, ts, 512, 2048, 2048, 2048, 0, 0, 0);
    }

    // ---- main: logits(H0) = t @ h^T ----
    {
        dim3 grd(NSEQ / 128, NSEQ / 128, HB);
        hmma_gemm3<false, 0><<<grd, 256, G3_SMEM>>>(
            ts, hs, nullptr, att, nullptr,
            512, 2048, 2048, 8192, sT, sT, 2048LL * 8192);
    }
    cudaEventRecord(evLog0, 0);

    // ---- s1: softmax(H0) + AV(H0) + MLP(H0) ----
    cudaStreamWaitEvent(s1, evLog0, 0);
    softmax_f16_kernel<<<HB * NSEQ, 256, 0, s1>>>(att, atth, cvec);
    {
        dim3 grd(512 / 128, NSEQ / 128, HB);
        hmma_av1<<<grd, 256, AV_SMEM, s1>>>((const uint8_t*)atth, vt16, o16);
    }
    {
        dim3 grd(512 / 128, (int)(hbRows / 128), 1);
        hmma_gemm1<true,  2><<<grd, 256, G1_SMEM, s1>>>(
            o16, w116, b1, nullptr, hid16, 512, 1024, 1024, 1024);
        hmma_gemm1<false, 0><<<grd, 256, G1_SMEM, s1>>>(
            hid16, w216, b2, out, nullptr, 512, 1024, 1024, 2048);
    }
    cudaEventRecord(evJoin, s1);

    // ---- main: logits(H1), softmax(H1), AV(H1), MLP(H1) ----
    {
        dim3 grd(NSEQ / 128, NSEQ / 128, HB);
        hmma_gemm3<false, 0><<<grd, 256, G3_SMEM>>>(
            ts + HB * sT, hs + HB * sT, nullptr,
            att + HB * sATTf, nullptr,
            512, 2048, 2048, 8192, sT, sT, 2048LL * 8192);
    }
    cudaStreamWaitEvent(0, evC, 0);
    softmax_f16_kernel<<<HB * NSEQ, 256>>>(att + HB * sATTf, atth + HB * sATTf,
                                           cvec + hbRows);
    cudaStreamWaitEvent(0, evVt, 0);
    {
        dim3 grd(512 / 128, NSEQ / 128, HB);
        hmma_av1<<<grd, 256, AV_SMEM>>>(
            (const uint8_t*)(atth + HB * sATTf),
            vt16 + (long long)HB * 512 * 4096,
            o16 + hbRows * 1024);
    }
    {
        dim3 grd(512 / 128, (int)(hbRows / 128), 1);
        hmma_gemm1<true,  2><<<grd, 256, G1_SMEM>>>(
            o16 + hbRows * 1024, w116, b1, nullptr, hid16 + hbRows * 1024,
            512, 1024, 1024, 1024);
        hmma_gemm1<false, 0><<<grd, 256, G1_SMEM>>>(
            hid16 + hbRows * 1024, w216, b2, out + hbRows * 512, nullptr,
            512, 1024, 1024, 2048);
    }

    // ---- join ----
    cudaStreamWaitEvent(0, evJoin, 0);
}